// round 4
// baseline (speedup 1.0000x reference)
#include <cuda_runtime.h>

#define SEQ   128
#define BSZ   1024
#define DIN   37
#define QDIM  11
#define HID   256
#define MSLOT 20
#define ROWS  (BSZ*MSLOT)   // 20480
#define SB    (SEQ*BSZ)     // 131072

#define BM 64
#define KC 64

// fused-scan tiling
#define TROWS 40                 // rows per tile = 2 batches
#define NTILES (ROWS/TROWS)      // 512
#define SCAN_GRID 148
#define SBSTR 258                // sB row stride (floats)

typedef unsigned long long ull;

// ---------------- scratch (no cudaMalloc allowed) ----------------
__device__ float g_mi[(size_t)SB*HID];
__device__ float g_tmp[(size_t)SB*HID];
__device__ float g_sentJ[(size_t)SB*HID];
__device__ float g_mem[(size_t)ROWS*HID];
__device__ float g_q[(size_t)BSZ*HID];
__device__ float g_a3[(size_t)MSLOT*HID];
__device__ float g_keyJ[(size_t)MSLOT*HID];
__device__ float g_cat[(size_t)BSZ*2*HID];

// ---------------- f32x2 helpers ----------------
__device__ __forceinline__ ull splat2(float a) {
    ull r; asm("mov.b64 %0, {%1, %1};" : "=l"(r) : "f"(a)); return r;
}
__device__ __forceinline__ void ffma2(ull& acc, ull a, ull b) {
    asm("fma.rn.f32x2 %0, %1, %2, %0;" : "+l"(acc) : "l"(a), "l"(b));
}
__device__ __forceinline__ float2 unpack2(ull v) {
    float2 f; asm("mov.b64 {%0, %1}, %2;" : "=f"(f.x), "=f"(f.y) : "l"(v)); return f;
}

// ---------------- generic GEMM: C[r][n] = act(sum_k A[r][k]*B[n][k] + bias[n]) ----------------
__global__ void __launch_bounds__(256) gemm256(
    const float* __restrict__ A, int lda, int rows, int K,
    const float* __restrict__ B, int ldb,
    const float* __restrict__ bias,
    float* __restrict__ C, int act)
{
    extern __shared__ float sm[];
    float* sA    = sm;                 // BM*KC
    float* sB    = sm + BM*KC;         // KC*257
    float* sBias = sB + KC*257;        // 256

    int tid = threadIdx.x;
    int rt = tid >> 5, ct = tid & 31;
    long r0 = (long)blockIdx.x * BM;

    sBias[tid] = bias ? bias[tid] : 0.f;

    float acc[8][8];
#pragma unroll
    for (int i = 0; i < 8; i++)
#pragma unroll
        for (int j = 0; j < 8; j++) acc[i][j] = 0.f;

    for (int k0 = 0; k0 < K; k0 += KC) {
#pragma unroll 4
        for (int t = tid; t < BM*KC; t += 256) {
            int row = t >> 6, kk = t & 63;
            int k = k0 + kk;
            long r = r0 + row;
            sA[t] = (k < K && r < rows) ? A[r*(long)lda + k] : 0.f;
        }
#pragma unroll 8
        for (int t = tid; t < 256*KC; t += 256) {
            int n = t >> 6, kk = t & 63;
            int k = k0 + kk;
            sB[kk*257 + n] = (k < K) ? B[(long)n*ldb + k] : 0.f;
        }
        __syncthreads();
#pragma unroll 8
        for (int kk = 0; kk < KC; kk++) {
            float a[8], bv[8];
#pragma unroll
            for (int i = 0; i < 8; i++) a[i] = sA[(rt*8 + i)*KC + kk];
#pragma unroll
            for (int j = 0; j < 8; j++) bv[j] = sB[kk*257 + ct + j*32];
#pragma unroll
            for (int i = 0; i < 8; i++)
#pragma unroll
                for (int j = 0; j < 8; j++) acc[i][j] = fmaf(a[i], bv[j], acc[i][j]);
        }
        __syncthreads();
    }
#pragma unroll
    for (int i = 0; i < 8; i++) {
        long row = r0 + rt*8 + i;
        if (row < rows) {
#pragma unroll
            for (int j = 0; j < 8; j++) {
                int col = ct + j*32;
                float v = acc[i][j] + sBias[col];
                if (act == 1) v = fmaxf(v, 0.f);
                C[row*256 + col] = v;
            }
        }
    }
}

// ---------------- fused persistent scan ----------------
// stage a KCx256 transposed weight panel: sB[kk][n] = W[n][k0+kk]
__device__ __forceinline__ void stage_panel(const float* __restrict__ W, int ldw,
                                            int k0, float* __restrict__ sB)
{
    int tid = threadIdx.x;
#pragma unroll 8
    for (int t = tid; t < 256*32; t += 256) {
        int n   = t >> 5;       // 0..255
        int kk2 = t & 31;       // 0..31, kk = 2*kk2
        float2 v = *(const float2*)(W + (long)n*ldw + k0 + 2*kk2);
        sB[(2*kk2  )*SBSTR + n] = v.x;
        sB[(2*kk2+1)*SBSTR + n] = v.y;
    }
}

__device__ __forceinline__ void compute_panel(const float* __restrict__ sBuf,
    const float* __restrict__ sA, int k0, ull acc[5][4], int rbase, int ct)
{
#pragma unroll 8
    for (int kk = 0; kk < KC; kk++) {
        const float* bp = sBuf + kk*SBSTR + 2*ct;
        ull b0 = *(const ull*)(bp);
        ull b1 = *(const ull*)(bp + 64);
        ull b2 = *(const ull*)(bp + 128);
        ull b3 = *(const ull*)(bp + 192);
#pragma unroll
        for (int i = 0; i < 5; i++) {
            ull a2 = splat2(sA[(rbase + i)*256 + k0 + kk]);
            ffma2(acc[i][0], a2, b0);
            ffma2(acc[i][1], a2, b1);
            ffma2(acc[i][2], a2, b2);
            ffma2(acc[i][3], a2, b3);
        }
    }
}

__global__ void __launch_bounds__(256) scan_kernel(
    const float* __restrict__ U_w, const float* __restrict__ U_b,
    const float* __restrict__ J_w, const float* __restrict__ J_b,
    const float* __restrict__ embed, const float* __restrict__ prelu_a,
    const float* __restrict__ mi, const float* __restrict__ sentJ,
    const float* __restrict__ keyJ, float* __restrict__ mem)
{
    extern __shared__ float sm[];
    float* sMem  = sm;                      // TROWS*256 = 10240
    float* sA1   = sMem + TROWS*256;        // 10240
    float* sB    = sA1  + TROWS*256;        // 2*KC*SBSTR = 33024
    float* sSent = sB   + 2*KC*SBSTR;       // 512
    float* sSJ   = sSent + 512;             // 512
    float* sUb   = sSJ   + 512;             // 256
    float* sJb   = sUb   + 256;             // 256
    float* sGate = sJb   + 256;             // 64

    int tid = threadIdx.x;
    int warp = tid >> 5, ct = tid & 31;
    int rbase = warp * 5;                   // 8 warps x 5 rows = 40
    float alpha = prelu_a[0];
    sUb[tid] = U_b[tid];
    sJb[tid] = J_b[tid];

    int t0 = (blockIdx.x     * NTILES) / SCAN_GRID;
    int t1 = ((blockIdx.x+1) * NTILES) / SCAN_GRID;

    for (int t = t0; t < t1; t++) {
        int r0 = t * TROWS;
        int b0 = r0 / MSLOT;                // = 2*t
        __syncthreads();                    // prev tile fully done before reloading sMem
        {
            const float4* g4 = (const float4*)(mem + (size_t)r0*256);
            float4* s4 = (float4*)sMem;
#pragma unroll 4
            for (int i = tid; i < TROWS*64; i += 256) s4[i] = g4[i];
        }

        for (int s = 0; s < SEQ; s++) {
            __syncthreads();                // sMem updates / sSJ reads from prev step done
            if (tid < 128) {
                const float4* g1 = (const float4*)(mi    + ((size_t)s*BSZ + b0)*256);
                const float4* g2 = (const float4*)(sentJ + ((size_t)s*BSZ + b0)*256);
                ((float4*)sSent)[tid] = g1[tid];
                ((float4*)sSJ)[tid]   = g2[tid];
            }
            __syncthreads();

            // ---- gate ----
#pragma unroll
            for (int i = 0; i < 5; i++) {
                int lr = rbase + i;
                int m  = lr % MSLOT;
                const float* se = sSent + ((lr >= MSLOT) ? 256 : 0);
                const float* em = embed + m*256;
                float p = 0.f;
#pragma unroll
                for (int kq = 0; kq < 8; kq++) {
                    int k = ct + kq*32;
                    p += se[k] * (sMem[lr*256 + k] + em[k]);
                }
#pragma unroll
                for (int o = 16; o > 0; o >>= 1) p += __shfl_xor_sync(0xffffffffu, p, o);
                if (ct == 0) sGate[lr] = 1.f / (1.f + expf(-p));
            }

            ull acc[5][4];
#pragma unroll
            for (int i = 0; i < 5; i++)
#pragma unroll
                for (int j = 0; j < 4; j++) acc[i][j] = 0ull;

            // ---- GEMM1: sMem @ U^T (double-buffered panels) ----
            stage_panel(U_w, 256, 0, sB);
            __syncthreads();
#pragma unroll 1
            for (int p = 0; p < 4; p++) {
                float* cur = sB + (p & 1) * KC * SBSTR;
                if (p < 3) stage_panel(U_w, 256, (p+1)*KC, sB + ((p+1)&1)*KC*SBSTR);
                compute_panel(cur, sMem, p*KC, acc, rbase, ct);
                __syncthreads();
            }

            // ---- A1 = relu(acc + U_b) ----
#pragma unroll
            for (int i = 0; i < 5; i++) {
#pragma unroll
                for (int j = 0; j < 4; j++) {
                    int col = 2*(ct + 32*j);
                    float2 v = unpack2(acc[i][j]);
                    v.x = fmaxf(v.x + sUb[col],   0.f);
                    v.y = fmaxf(v.y + sUb[col+1], 0.f);
                    *(float2*)(sA1 + (rbase+i)*256 + col) = v;
                    acc[i][j] = 0ull;
                }
            }
            __syncthreads();

            // ---- GEMM2: A1 @ J[:,0:256]^T ----
            stage_panel(J_w, 768, 0, sB);
            __syncthreads();
#pragma unroll 1
            for (int p = 0; p < 4; p++) {
                float* cur = sB + (p & 1) * KC * SBSTR;
                if (p < 3) stage_panel(J_w, 768, (p+1)*KC, sB + ((p+1)&1)*KC*SBSTR);
                compute_panel(cur, sA1, p*KC, acc, rbase, ct);
                __syncthreads();
            }

            // ---- epilogue: prelu, gated update, normalize, write sMem in place ----
#pragma unroll
            for (int i = 0; i < 5; i++) {
                int lr = rbase + i;
                int m  = lr % MSLOT;
                float g = sGate[lr];
                const float* sj = sSJ + ((lr >= MSLOT) ? 256 : 0);
                const float* kj = keyJ + m*256;
                float u[8];
                float ss = 0.f;
#pragma unroll
                for (int j = 0; j < 4; j++) {
                    int col = 2*(ct + 32*j);
                    float2 c = unpack2(acc[i][j]);
                    float c0 = c.x + sJb[col]   + sj[col]   + kj[col];
                    float c1 = c.y + sJb[col+1] + sj[col+1] + kj[col+1];
                    c0 = c0 > 0.f ? c0 : alpha * c0;
                    c1 = c1 > 0.f ? c1 : alpha * c1;
                    float u0 = sMem[lr*256 + col]     + g * c0;
                    float u1 = sMem[lr*256 + col + 1] + g * c1;
                    u[2*j] = u0; u[2*j+1] = u1;
                    ss += u0*u0 + u1*u1;
                }
#pragma unroll
                for (int o = 16; o > 0; o >>= 1) ss += __shfl_xor_sync(0xffffffffu, ss, o);
                float inv = 1.f / (sqrtf(ss) + 1e-12f);
#pragma unroll
                for (int j = 0; j < 4; j++) {
                    int col = 2*(ct + 32*j);
                    float2 w; w.x = u[2*j]*inv; w.y = u[2*j+1]*inv;
                    *(float2*)(sMem + lr*256 + col) = w;
                }
            }
        }

        __syncthreads();
        {
            const float4* s4 = (const float4*)sMem;
            float4* g4 = (float4*)(mem + (size_t)r0*256);
#pragma unroll 4
            for (int i = tid; i < TROWS*64; i += 256) g4[i] = s4[i];
        }
    }
}

// ---------------- memories init: mem[b*20+m][d] = embed[m][d] ----------------
__global__ void init_mem_kernel(const float* __restrict__ embed, float* __restrict__ mem)
{
    long idx = (long)blockIdx.x * 256 + threadIdx.x;
    int d = idx & 255;
    long rm = idx >> 8;
    int m = (int)(rm % MSLOT);
    mem[idx] = embed[m*256 + d];
}

// ---------------- attention + concat ----------------
__global__ void __launch_bounds__(256) attn_kernel(
    const float* __restrict__ mem, const float* __restrict__ q, float* __restrict__ cat)
{
    __shared__ float sQ[256];
    __shared__ float sM[MSLOT*256];
    __shared__ float sE[MSLOT];
    int b = blockIdx.x, tid = threadIdx.x;
    sQ[tid] = q[(long)b*256 + tid];
    for (int t = tid; t < MSLOT*256; t += 256) sM[t] = mem[(long)b*MSLOT*256 + t];
    __syncthreads();
    int w = tid >> 5, l = tid & 31;
    for (int m = w; m < MSLOT; m += 8) {
        float p = 0.f;
        for (int k = l; k < 256; k += 32) p += sM[m*256 + k] * sQ[k];
#pragma unroll
        for (int o = 16; o > 0; o >>= 1) p += __shfl_xor_sync(0xffffffffu, p, o);
        if (l == 0) sE[m] = p;
    }
    __syncthreads();
    float mx = -1e30f;
    for (int m = 0; m < MSLOT; m++) mx = fmaxf(mx, sE[m]);
    float sum = 0.f;
    for (int m = 0; m < MSLOT; m++) sum += expf(sE[m] - mx);
    float att = 0.f;
    for (int m = 0; m < MSLOT; m++) att += sM[m*256 + tid] * expf(sE[m] - mx);
    att /= sum;
    cat[(long)b*512 + tid]       = sQ[tid];
    cat[(long)b*512 + 256 + tid] = att;
}

// ---------------- host launcher ----------------
extern "C" void kernel_launch(void* const* d_in, const int* in_sizes, int n_in,
                              void* d_out, int out_size)
{
    const float* memory_inputs = (const float*)d_in[0];
    const float* question      = (const float*)d_in[1];
    const float* C_w = (const float*)d_in[2];
    const float* C_b = (const float*)d_in[3];
    const float* Q_w = (const float*)d_in[4];
    const float* Q_b = (const float*)d_in[5];
    const float* H_w = (const float*)d_in[6];
    const float* H_b = (const float*)d_in[7];
    const float* U_w = (const float*)d_in[8];
    const float* U_b = (const float*)d_in[9];
    const float* V_w = (const float*)d_in[10];
    const float* V_b = (const float*)d_in[11];
    const float* W_w = (const float*)d_in[12];
    const float* W_b = (const float*)d_in[13];
    const float* J_w = (const float*)d_in[14];
    const float* J_b = (const float*)d_in[15];
    const float* prelu_a = (const float*)d_in[16];
    const float* embed   = (const float*)d_in[17];
    float* out = (float*)d_out;

    size_t gemm_smem = (size_t)(BM*KC + KC*257 + 256) * sizeof(float);
    size_t scan_smem = (size_t)(TROWS*256 + TROWS*256 + 2*KC*SBSTR + 512 + 512 + 256 + 256 + 64) * sizeof(float);
    cudaFuncSetAttribute(gemm256,     cudaFuncAttributeMaxDynamicSharedMemorySize, (int)gemm_smem);
    cudaFuncSetAttribute(scan_kernel, cudaFuncAttributeMaxDynamicSharedMemorySize, (int)scan_smem);

    float *mi, *tmp, *sentJ, *memb, *q, *a3, *keyJ, *cat;
    cudaGetSymbolAddress((void**)&mi,    g_mi);
    cudaGetSymbolAddress((void**)&tmp,   g_tmp);
    cudaGetSymbolAddress((void**)&sentJ, g_sentJ);
    cudaGetSymbolAddress((void**)&memb,  g_mem);
    cudaGetSymbolAddress((void**)&q,     g_q);
    cudaGetSymbolAddress((void**)&a3,    g_a3);
    cudaGetSymbolAddress((void**)&keyJ,  g_keyJ);
    cudaGetSymbolAddress((void**)&cat,   g_cat);

    // init recurrent state
    init_mem_kernel<<<ROWS, 256>>>(embed, memb);

    // precompute (loop-invariant parts)
    gemm256<<<SB/BM, 256, gemm_smem>>>(memory_inputs, DIN, SB, DIN, C_w, DIN, C_b, mi, 1);
    gemm256<<<BSZ/BM, 256, gemm_smem>>>(question, QDIM, BSZ, QDIM, Q_w, QDIM, Q_b, q, 1);
    gemm256<<<SB/BM, 256, gemm_smem>>>(mi, HID, SB, HID, V_w, HID, V_b, tmp, 1);
    gemm256<<<SB/BM, 256, gemm_smem>>>(tmp, HID, SB, HID, J_w + 256, 768, (const float*)0, sentJ, 0);
    gemm256<<<1, 256, gemm_smem>>>(embed, HID, MSLOT, HID, W_w, HID, W_b, a3, 1);
    gemm256<<<1, 256, gemm_smem>>>(a3, HID, MSLOT, HID, J_w + 512, 768, (const float*)0, keyJ, 0);

    // fused persistent scan: one launch, state resident in SMEM
    scan_kernel<<<SCAN_GRID, 256, scan_smem>>>(U_w, U_b, J_w, J_b, embed, prelu_a,
                                               mi, sentJ, keyJ, memb);

    // attention + concat, then final projection
    attn_kernel<<<BSZ, 256>>>(memb, q, cat);
    gemm256<<<BSZ/BM, 256, gemm_smem>>>(cat, 2*HID, BSZ, 2*HID, H_w, 2*HID, H_b, out, 1);
}

// round 5
// speedup vs baseline: 1.4652x; 1.4652x over previous
#include <cuda_runtime.h>

#define SEQ   128
#define BSZ   1024
#define DIN   37
#define QDIM  11
#define HID   256
#define MSLOT 20
#define ROWS  (BSZ*MSLOT)   // 20480
#define SB    (SEQ*BSZ)     // 131072

#define BM 64
#define KC 64

// fused-scan tiling
#define TROWS 80                 // rows per tile = 4 batches exactly
#define RPT   10                 // rows per thread (8 warps x 10 = 80)
#define KCP   16                 // panel K depth
#define NPAN  32                 // panels per step (16 U + 16 J1)
#define NTILES (ROWS/TROWS)      // 256
#define SCAN_GRID 148

typedef unsigned long long ull;

// ---------------- scratch (no cudaMalloc allowed) ----------------
__device__ float g_mi[(size_t)SB*HID];
__device__ float g_tmp[(size_t)SB*HID];
__device__ float g_sentJ[(size_t)SB*HID];
__device__ float g_mem[(size_t)ROWS*HID];
__device__ float g_q[(size_t)BSZ*HID];
__device__ float g_a3[(size_t)MSLOT*HID];
__device__ float g_keyJ[(size_t)MSLOT*HID];
__device__ float g_cat[(size_t)BSZ*2*HID];
__device__ float g_gateE[(size_t)SB*MSLOT];          // sent . embed per (s,b,m)
__device__ float g_wT[4*(size_t)HID*HID];            // Ut, J1t, Vt, J2t (k-major)

// ---------------- f32x2 / cp.async helpers ----------------
__device__ __forceinline__ ull splat2(float a) {
    ull r; asm("mov.b64 %0, {%1, %1};" : "=l"(r) : "f"(a)); return r;
}
__device__ __forceinline__ void ffma2(ull& acc, ull a, ull b) {
    asm("fma.rn.f32x2 %0, %1, %2, %0;" : "+l"(acc) : "l"(a), "l"(b));
}
__device__ __forceinline__ float2 unpack2(ull v) {
    float2 f; asm("mov.b64 {%0, %1}, %2;" : "=f"(f.x), "=f"(f.y) : "l"(v)); return f;
}
__device__ __forceinline__ unsigned smem_u32(const void* p) {
    unsigned r;
    asm("{ .reg .u64 t; cvta.to.shared.u64 t, %1; cvt.u32.u64 %0, t; }" : "=r"(r) : "l"(p));
    return r;
}
__device__ __forceinline__ void cp_async16(unsigned saddr, const void* gptr) {
    asm volatile("cp.async.cg.shared.global [%0], [%1], 16;" :: "r"(saddr), "l"(gptr));
}
__device__ __forceinline__ void cp_commit() {
    asm volatile("cp.async.commit_group;");
}
template <int N>
__device__ __forceinline__ void cp_wait() {
    asm volatile("cp.async.wait_group %0;" :: "n"(N));
}

// issue one KCP x 256 panel (float4 copies, conflict-free)
__device__ __forceinline__ void issue_panel(const float* __restrict__ src,
                                            float* __restrict__ dst, int tid)
{
    unsigned d = smem_u32(dst) + (unsigned)tid * 16u;
    const float4* g = (const float4*)src + tid;
#pragma unroll
    for (int q = 0; q < (KCP*256)/(256*4); q++)   // 4 chunks
        cp_async16(d + q*256*16, g + q*256);
    cp_commit();
}

// core f32x2 micro-GEMM over one panel: acc[i][j] over rows rbase..rbase+R-1
template <int R>
__device__ __forceinline__ void compute_panel16(const float* __restrict__ pan,
    const float* __restrict__ A, int k0, ull acc[R][4], int rbase, int ct)
{
#pragma unroll
    for (int kk = 0; kk < KCP; kk++) {
        const float* bp = pan + kk*256 + 2*ct;
        ull b0 = *(const ull*)(bp);
        ull b1 = *(const ull*)(bp + 64);
        ull b2 = *(const ull*)(bp + 128);
        ull b3 = *(const ull*)(bp + 192);
#pragma unroll
        for (int i = 0; i < R; i++) {
            ull a2 = splat2(A[(rbase + i)*256 + k0 + kk]);
            ffma2(acc[i][0], a2, b0);
            ffma2(acc[i][1], a2, b1);
            ffma2(acc[i][2], a2, b2);
            ffma2(acc[i][3], a2, b3);
        }
    }
}

// ---------------- generic scalar GEMM (small-K / odd-K cases) ----------------
__global__ void __launch_bounds__(256) gemm256(
    const float* __restrict__ A, int lda, int rows, int K,
    const float* __restrict__ B, int ldb,
    const float* __restrict__ bias,
    float* __restrict__ C, int act)
{
    extern __shared__ float sm[];
    float* sA    = sm;                 // BM*KC
    float* sB    = sm + BM*KC;         // KC*257
    float* sBias = sB + KC*257;        // 256

    int tid = threadIdx.x;
    int rt = tid >> 5, ct = tid & 31;
    long r0 = (long)blockIdx.x * BM;

    sBias[tid] = bias ? bias[tid] : 0.f;

    float acc[8][8];
#pragma unroll
    for (int i = 0; i < 8; i++)
#pragma unroll
        for (int j = 0; j < 8; j++) acc[i][j] = 0.f;

    for (int k0 = 0; k0 < K; k0 += KC) {
#pragma unroll 4
        for (int t = tid; t < BM*KC; t += 256) {
            int row = t >> 6, kk = t & 63;
            int k = k0 + kk;
            long r = r0 + row;
            sA[t] = (k < K && r < rows) ? A[r*(long)lda + k] : 0.f;
        }
#pragma unroll 8
        for (int t = tid; t < 256*KC; t += 256) {
            int n = t >> 6, kk = t & 63;
            int k = k0 + kk;
            sB[kk*257 + n] = (k < K) ? B[(long)n*ldb + k] : 0.f;
        }
        __syncthreads();
#pragma unroll 8
        for (int kk = 0; kk < KC; kk++) {
            float a[8], bv[8];
#pragma unroll
            for (int i = 0; i < 8; i++) a[i] = sA[(rt*8 + i)*KC + kk];
#pragma unroll
            for (int j = 0; j < 8; j++) bv[j] = sB[kk*257 + ct + j*32];
#pragma unroll
            for (int i = 0; i < 8; i++)
#pragma unroll
                for (int j = 0; j < 8; j++) acc[i][j] = fmaf(a[i], bv[j], acc[i][j]);
        }
        __syncthreads();
    }
#pragma unroll
    for (int i = 0; i < 8; i++) {
        long row = r0 + rt*8 + i;
        if (row < rows) {
#pragma unroll
            for (int j = 0; j < 8; j++) {
                int col = ct + j*32;
                float v = acc[i][j] + sBias[col];
                if (act == 1) v = fmaxf(v, 0.f);
                C[row*256 + col] = v;
            }
        }
    }
}

// ---------------- f32x2 GEMM, K=256, N=256, Bt pre-transposed (k-major) ----------------
__global__ void __launch_bounds__(256,2) gemm_ffma2(
    const float* __restrict__ A,      // [rows][256]
    const float* __restrict__ Bt,     // [256][256] k-major
    const float* __restrict__ bias,
    float* __restrict__ C, int act)
{
    extern __shared__ float sm[];
    float* sA    = sm;                // 64*256 = 16384
    float* sPan  = sA + 64*256;       // 3*KCP*256 = 12288
    float* sBias = sPan + 3*KCP*256;  // 256

    int tid = threadIdx.x;
    int warp = tid >> 5, ct = tid & 31;
    int rbase = warp * 8;
    long r0 = (long)blockIdx.x * 64;

    sBias[tid] = bias ? bias[tid] : 0.f;
    // load A tile (coalesced float4)
    {
        const float4* g4 = (const float4*)(A + r0*256);
        float4* s4 = (float4*)sA;
#pragma unroll 4
        for (int i = tid; i < 64*64; i += 256) s4[i] = g4[i];
    }
    issue_panel(Bt + 0*KCP*256, sPan + 0*KCP*256, tid);
    issue_panel(Bt + 1*KCP*256, sPan + 1*KCP*256, tid);

    ull acc[8][4];
#pragma unroll
    for (int i = 0; i < 8; i++)
#pragma unroll
        for (int j = 0; j < 4; j++) acc[i][j] = 0ull;

    for (int p = 0; p < 16; p++) {
        if (p < 15) cp_wait<1>(); else cp_wait<0>();
        __syncthreads();
        if (p + 2 < 16)
            issue_panel(Bt + (p+2)*KCP*256, sPan + ((p+2)%3)*KCP*256, tid);
        compute_panel16<8>(sPan + (p%3)*KCP*256, sA, p*KCP, acc, rbase, ct);
    }

#pragma unroll
    for (int i = 0; i < 8; i++) {
        long row = r0 + rbase + i;
#pragma unroll
        for (int j = 0; j < 4; j++) {
            int col = 2*(ct + 32*j);
            float2 v = unpack2(acc[i][j]);
            v.x += sBias[col];
            v.y += sBias[col+1];
            if (act) { v.x = fmaxf(v.x, 0.f); v.y = fmaxf(v.y, 0.f); }
            *(float2*)(C + row*256 + col) = v;
        }
    }
}

// ---------------- 256x256 transpose: out[k][256+n] = in[n][ldin+k] ----------------
__global__ void transpose256(const float* __restrict__ in, int ldin, float* __restrict__ out)
{
    __shared__ float tl[32][33];
    int bx = blockIdx.x*32, by = blockIdx.y*32;  // bx: k, by: n
    int tx = threadIdx.x, ty = threadIdx.y;      // block(32,8)
#pragma unroll
    for (int r = 0; r < 4; r++)
        tl[ty + 8*r][tx] = in[(long)(by + ty + 8*r)*ldin + bx + tx];
    __syncthreads();
#pragma unroll
    for (int r = 0; r < 4; r++)
        out[(long)(bx + ty + 8*r)*256 + by + tx] = tl[tx][ty + 8*r];
}

// ---------------- gateE = mi @ embed^T  (SB x 20) ----------------
__global__ void __launch_bounds__(256) gatee_kernel(
    const float* __restrict__ mi, const float* __restrict__ embed, float* __restrict__ out)
{
    extern __shared__ float sm[];
    float* sMi = sm;            // 64*256
    float* sE  = sm + 64*256;   // 20*256
    int tid = threadIdx.x, ct = tid & 31;
    long r0 = (long)blockIdx.x * 64;
    {
        const float4* g4 = (const float4*)(mi + r0*256);
        float4* s4 = (float4*)sMi;
#pragma unroll 4
        for (int i = tid; i < 64*64; i += 256) s4[i] = g4[i];
        const float4* e4 = (const float4*)embed;
        float4* se4 = (float4*)sE;
        for (int i = tid; i < 20*64; i += 256) se4[i] = e4[i];
    }
    __syncthreads();
#pragma unroll
    for (int q = 0; q < 5; q++) {
        int o = q*256 + tid;            // 0..1279
        int row = o / 20, m = o % 20;
        float acc = 0.f;
#pragma unroll 8
        for (int k = 0; k < 256; k++) {
            int kr = (k + ct*8) & 255;  // rotate to avoid bank conflicts
            acc += sMi[row*256 + kr] * sE[m*256 + kr];
        }
        out[r0*20 + o] = acc;
    }
}

// ---------------- fused persistent scan (state SMEM-resident, weights cp.async) ----------------
__global__ void __launch_bounds__(256,1) scan_kernel(
    const float* __restrict__ Ut, const float* __restrict__ J1t,
    const float* __restrict__ U_b, const float* __restrict__ J_b,
    const float* __restrict__ prelu_a,
    const float* __restrict__ mi, const float* __restrict__ sentJ,
    const float* __restrict__ gateE, const float* __restrict__ keyJ,
    float* __restrict__ mem)
{
    extern __shared__ float sm[];
    float* sMem  = sm;                       // 80*256 = 20480
    float* sA1   = sMem + TROWS*256;         // 20480
    float* sPan  = sA1  + TROWS*256;         // 3*16*256 = 12288
    float* sSent = sPan + 3*KCP*256;         // 4*256
    float* sSJ   = sSent + 4*256;            // 4*256
    float* sUb   = sSJ   + 4*256;            // 256
    float* sJb   = sUb   + 256;              // 256

    int tid = threadIdx.x;
    int warp = tid >> 5, ct = tid & 31;
    int rbase = warp * RPT;
    float alpha = prelu_a[0];
    sUb[tid] = U_b[tid];
    sJb[tid] = J_b[tid];

    int t0 = (blockIdx.x     * NTILES) / SCAN_GRID;
    int t1 = ((blockIdx.x+1) * NTILES) / SCAN_GRID;

    for (int t = t0; t < t1; t++) {
        int r0 = t * TROWS;
        int b0 = t * 4;                       // 4 batches per tile exactly
        __syncthreads();                      // prev tile fully done
        {
            const float4* g4 = (const float4*)(mem + (size_t)r0*256);
            float4* s4 = (float4*)sMem;
#pragma unroll 4
            for (int i = tid; i < TROWS*64; i += 256) s4[i] = g4[i];
        }

        for (int s = 0; s < SEQ; s++) {
            __syncthreads();                  // prev epilogue done (sSJ), sMem tile loaded
            {
                const float4* g1 = (const float4*)(mi    + ((size_t)s*BSZ + b0)*256);
                const float4* g2 = (const float4*)(sentJ + ((size_t)s*BSZ + b0)*256);
                ((float4*)sSent)[tid] = g1[tid];   // 256 float4 = 4 batches
                ((float4*)sSJ)[tid]   = g2[tid];
            }
            // warm the panel pipeline (buffers 0,1 free by loop-barrier argument)
            issue_panel(Ut + 0*KCP*256, sPan + 0*KCP*256, tid);
            issue_panel(Ut + 1*KCP*256, sPan + 1*KCP*256, tid);
            __syncthreads();                  // sSent/sSJ visible

            // ---- gate (sent.mem in SMEM + precomputed sent.embed) ----
            float gv[RPT];
#pragma unroll
            for (int i = 0; i < RPT; i++) {
                int lr = rbase + i;
                const float* se = sSent + (lr/20)*256;
                float p = 0.f;
#pragma unroll
                for (int q = 0; q < 8; q++) {
                    int k = ct + q*32;
                    p += se[k] * sMem[lr*256 + k];
                }
#pragma unroll
                for (int o = 16; o > 0; o >>= 1) p += __shfl_xor_sync(0xffffffffu, p, o);
                p += gateE[(size_t)s*ROWS + r0 + lr];
                gv[i] = 1.f / (1.f + expf(-p));
            }

            ull acc[RPT][4];
#pragma unroll
            for (int i = 0; i < RPT; i++)
#pragma unroll
                for (int j = 0; j < 4; j++) acc[i][j] = 0ull;

            // ---- 32 panels: 16 of U (GEMM1 on sMem), 16 of J1 (GEMM2 on sA1) ----
            for (int p = 0; p < NPAN; p++) {
                if (p < NPAN-1) cp_wait<1>(); else cp_wait<0>();
                __syncthreads();
                int pn = p + 2;
                if (pn < NPAN) {
                    const float* src = (pn < 16) ? (Ut + pn*KCP*256)
                                                 : (J1t + (pn-16)*KCP*256);
                    issue_panel(src, sPan + (pn%3)*KCP*256, tid);
                }
                const float* A = (p < 16) ? sMem : sA1;
                compute_panel16<RPT>(sPan + (p%3)*KCP*256, A, (p & 15)*KCP, acc, rbase, ct);

                if (p == 15) {
                    // A1 = relu(acc + U_b), then reset acc for GEMM2
#pragma unroll
                    for (int i = 0; i < RPT; i++) {
#pragma unroll
                        for (int j = 0; j < 4; j++) {
                            int col = 2*(ct + 32*j);
                            float2 v = unpack2(acc[i][j]);
                            v.x = fmaxf(v.x + sUb[col],   0.f);
                            v.y = fmaxf(v.y + sUb[col+1], 0.f);
                            *(float2*)(sA1 + (rbase+i)*256 + col) = v;
                            acc[i][j] = 0ull;
                        }
                    }
                }
            }

            // ---- epilogue: prelu, gated update, normalize; sMem in place (warp-local) ----
#pragma unroll
            for (int i = 0; i < RPT; i++) {
                int lr = rbase + i;
                int m  = lr % MSLOT;
                float g = gv[i];
                const float* sj = sSJ + (lr/20)*256;
                const float* kj = keyJ + m*256;
                float u[8];
                float ss = 0.f;
#pragma unroll
                for (int j = 0; j < 4; j++) {
                    int col = 2*(ct + 32*j);
                    float2 c = unpack2(acc[i][j]);
                    float2 kv = *(const float2*)(kj + col);
                    float c0 = c.x + sJb[col]   + sj[col]   + kv.x;
                    float c1 = c.y + sJb[col+1] + sj[col+1] + kv.y;
                    c0 = c0 > 0.f ? c0 : alpha * c0;
                    c1 = c1 > 0.f ? c1 : alpha * c1;
                    float u0 = sMem[lr*256 + col]     + g * c0;
                    float u1 = sMem[lr*256 + col + 1] + g * c1;
                    u[2*j] = u0; u[2*j+1] = u1;
                    ss += u0*u0 + u1*u1;
                }
#pragma unroll
                for (int o = 16; o > 0; o >>= 1) ss += __shfl_xor_sync(0xffffffffu, ss, o);
                float inv = 1.f / (sqrtf(ss) + 1e-12f);
#pragma unroll
                for (int j = 0; j < 4; j++) {
                    int col = 2*(ct + 32*j);
                    float2 w; w.x = u[2*j]*inv; w.y = u[2*j+1]*inv;
                    *(float2*)(sMem + lr*256 + col) = w;
                }
            }
        }

        __syncthreads();
        {
            const float4* s4 = (const float4*)sMem;
            float4* g4 = (float4*)(mem + (size_t)r0*256);
#pragma unroll 4
            for (int i = tid; i < TROWS*64; i += 256) g4[i] = s4[i];
        }
    }
}

// ---------------- memories init: mem[b*20+m][d] = embed[m][d] ----------------
__global__ void init_mem_kernel(const float* __restrict__ embed, float* __restrict__ mem)
{
    long idx = (long)blockIdx.x * 256 + threadIdx.x;
    int d = idx & 255;
    long rm = idx >> 8;
    int m = (int)(rm % MSLOT);
    mem[idx] = embed[m*256 + d];
}

// ---------------- attention + concat ----------------
__global__ void __launch_bounds__(256) attn_kernel(
    const float* __restrict__ mem, const float* __restrict__ q, float* __restrict__ cat)
{
    __shared__ float sQ[256];
    __shared__ float sM[MSLOT*256];
    __shared__ float sE[MSLOT];
    int b = blockIdx.x, tid = threadIdx.x;
    sQ[tid] = q[(long)b*256 + tid];
    for (int t = tid; t < MSLOT*256; t += 256) sM[t] = mem[(long)b*MSLOT*256 + t];
    __syncthreads();
    int w = tid >> 5, l = tid & 31;
    for (int m = w; m < MSLOT; m += 8) {
        float p = 0.f;
        for (int k = l; k < 256; k += 32) p += sM[m*256 + k] * sQ[k];
#pragma unroll
        for (int o = 16; o > 0; o >>= 1) p += __shfl_xor_sync(0xffffffffu, p, o);
        if (l == 0) sE[m] = p;
    }
    __syncthreads();
    float mx = -1e30f;
    for (int m = 0; m < MSLOT; m++) mx = fmaxf(mx, sE[m]);
    float sum = 0.f;
    for (int m = 0; m < MSLOT; m++) sum += expf(sE[m] - mx);
    float att = 0.f;
    for (int m = 0; m < MSLOT; m++) att += sM[m*256 + tid] * expf(sE[m] - mx);
    att /= sum;
    cat[(long)b*512 + tid]       = sQ[tid];
    cat[(long)b*512 + 256 + tid] = att;
}

// ---------------- host launcher ----------------
extern "C" void kernel_launch(void* const* d_in, const int* in_sizes, int n_in,
                              void* d_out, int out_size)
{
    const float* memory_inputs = (const float*)d_in[0];
    const float* question      = (const float*)d_in[1];
    const float* C_w = (const float*)d_in[2];
    const float* C_b = (const float*)d_in[3];
    const float* Q_w = (const float*)d_in[4];
    const float* Q_b = (const float*)d_in[5];
    const float* H_w = (const float*)d_in[6];
    const float* H_b = (const float*)d_in[7];
    const float* U_w = (const float*)d_in[8];
    const float* U_b = (const float*)d_in[9];
    const float* V_w = (const float*)d_in[10];
    const float* V_b = (const float*)d_in[11];
    const float* W_w = (const float*)d_in[12];
    const float* W_b = (const float*)d_in[13];
    const float* J_w = (const float*)d_in[14];
    const float* J_b = (const float*)d_in[15];
    const float* prelu_a = (const float*)d_in[16];
    const float* embed   = (const float*)d_in[17];
    float* out = (float*)d_out;

    size_t gemm_smem  = (size_t)(BM*KC + KC*257 + 256) * sizeof(float);
    size_t gx2_smem   = (size_t)(64*256 + 3*KCP*256 + 256) * sizeof(float);
    size_t scan_smem  = (size_t)(TROWS*256*2 + 3*KCP*256 + 4*256*2 + 512) * sizeof(float);
    size_t gatee_smem = (size_t)(64*256 + 20*256) * sizeof(float);
    cudaFuncSetAttribute(gemm256,      cudaFuncAttributeMaxDynamicSharedMemorySize, (int)gemm_smem);
    cudaFuncSetAttribute(gemm_ffma2,   cudaFuncAttributeMaxDynamicSharedMemorySize, (int)gx2_smem);
    cudaFuncSetAttribute(scan_kernel,  cudaFuncAttributeMaxDynamicSharedMemorySize, (int)scan_smem);
    cudaFuncSetAttribute(gatee_kernel, cudaFuncAttributeMaxDynamicSharedMemorySize, (int)gatee_smem);

    float *mi, *tmp, *sentJ, *memb, *q, *a3, *keyJ, *cat, *gateE, *wT;
    cudaGetSymbolAddress((void**)&mi,    g_mi);
    cudaGetSymbolAddress((void**)&tmp,   g_tmp);
    cudaGetSymbolAddress((void**)&sentJ, g_sentJ);
    cudaGetSymbolAddress((void**)&memb,  g_mem);
    cudaGetSymbolAddress((void**)&q,     g_q);
    cudaGetSymbolAddress((void**)&a3,    g_a3);
    cudaGetSymbolAddress((void**)&keyJ,  g_keyJ);
    cudaGetSymbolAddress((void**)&cat,   g_cat);
    cudaGetSymbolAddress((void**)&gateE, g_gateE);
    cudaGetSymbolAddress((void**)&wT,    g_wT);
    float* Ut  = wT;
    float* J1t = wT + (size_t)HID*HID;
    float* Vt  = wT + 2*(size_t)HID*HID;
    float* J2t = wT + 3*(size_t)HID*HID;

    // weight transposes (one-time, tiny)
    dim3 tb(32, 8), tg(8, 8);
    transpose256<<<tg, tb>>>(U_w, 256, Ut);
    transpose256<<<tg, tb>>>(J_w, 768, J1t);
    transpose256<<<tg, tb>>>(V_w, 256, Vt);
    transpose256<<<tg, tb>>>(J_w + 256, 768, J2t);

    // init recurrent state
    init_mem_kernel<<<ROWS, 256>>>(embed, memb);

    // precompute
    gemm256<<<SB/BM, 256, gemm_smem>>>(memory_inputs, DIN, SB, DIN, C_w, DIN, C_b, mi, 1);
    gemm256<<<BSZ/BM, 256, gemm_smem>>>(question, QDIM, BSZ, QDIM, Q_w, QDIM, Q_b, q, 1);
    gatee_kernel<<<SB/64, 256, gatee_smem>>>(mi, embed, gateE);
    gemm_ffma2<<<SB/64, 256, gx2_smem>>>(mi, Vt, V_b, tmp, 1);
    gemm_ffma2<<<SB/64, 256, gx2_smem>>>(tmp, J2t, (const float*)0, sentJ, 0);
    gemm256<<<1, 256, gemm_smem>>>(embed, HID, MSLOT, HID, W_w, HID, W_b, a3, 1);
    gemm256<<<1, 256, gemm_smem>>>(a3, HID, MSLOT, HID, J_w + 512, 768, (const float*)0, keyJ, 0);

    // fused persistent scan
    scan_kernel<<<SCAN_GRID, 256, scan_smem>>>(Ut, J1t, U_b, J_b, prelu_a,
                                               mi, sentJ, gateE, keyJ, memb);

    // attention + concat, then final projection
    attn_kernel<<<BSZ, 256>>>(memb, q, cat);
    gemm256<<<BSZ/BM, 256, gemm_smem>>>(cat, 2*HID, BSZ, 2*HID, H_w, 2*HID, H_b, out, 1);
}

// round 6
// speedup vs baseline: 1.4657x; 1.0003x over previous
#include <cuda_runtime.h>

#define SEQ   128
#define BSZ   1024
#define DIN   37
#define QDIM  11
#define HID   256
#define MSLOT 20
#define ROWS  (BSZ*MSLOT)   // 20480
#define SB    (SEQ*BSZ)     // 131072

#define BM 64
#define KC 64

// fused-scan tiling
#define TROWS 80                 // rows per tile = 4 batches exactly
#define RPT   10                 // rows per thread (8 warps x 10 = 80)
#define KCP   16                 // panel K depth
#define NPAN  32                 // panels per step (16 U + 16 J1)
#define NTILES (ROWS/TROWS)      // 256
#define SCAN_GRID 148

typedef unsigned long long ull;

// ---------------- scratch (no cudaMalloc allowed) ----------------
__device__ float g_mi[(size_t)SB*HID];
__device__ float g_tmp[(size_t)SB*HID];
__device__ float g_sentJ[(size_t)SB*HID];
__device__ float g_mem[(size_t)ROWS*HID];
__device__ float g_q[(size_t)BSZ*HID];
__device__ float g_a3[(size_t)MSLOT*HID];
__device__ float g_keyJ[(size_t)MSLOT*HID];
__device__ float g_cat[(size_t)BSZ*2*HID];
__device__ float g_gateE[(size_t)SB*MSLOT];          // sent . embed per (s,b,m)
__device__ float g_wT[4*(size_t)HID*HID];            // Ut, J1t, Vt, J2t (k-major)

// ---------------- f32x2 / cp.async helpers ----------------
__device__ __forceinline__ ull splat2(float a) {
    ull r; asm("mov.b64 %0, {%1, %1};" : "=l"(r) : "f"(a)); return r;
}
__device__ __forceinline__ void ffma2(ull& acc, ull a, ull b) {
    asm("fma.rn.f32x2 %0, %1, %2, %0;" : "+l"(acc) : "l"(a), "l"(b));
}
__device__ __forceinline__ float2 unpack2(ull v) {
    float2 f; asm("mov.b64 {%0, %1}, %2;" : "=f"(f.x), "=f"(f.y) : "l"(v)); return f;
}
__device__ __forceinline__ unsigned smem_u32(const void* p) {
    unsigned r;
    asm("{ .reg .u64 t; cvta.to.shared.u64 t, %1; cvt.u32.u64 %0, t; }" : "=r"(r) : "l"(p));
    return r;
}
__device__ __forceinline__ void cp_async16(unsigned saddr, const void* gptr) {
    asm volatile("cp.async.cg.shared.global [%0], [%1], 16;" :: "r"(saddr), "l"(gptr));
}
__device__ __forceinline__ void cp_commit() {
    asm volatile("cp.async.commit_group;");
}
template <int N>
__device__ __forceinline__ void cp_wait() {
    asm volatile("cp.async.wait_group %0;" :: "n"(N));
}

// issue one KCP x 256 panel (float4 copies, conflict-free)
__device__ __forceinline__ void issue_panel(const float* __restrict__ src,
                                            float* __restrict__ dst, int tid)
{
    unsigned d = smem_u32(dst) + (unsigned)tid * 16u;
    const float4* g = (const float4*)src + tid;
#pragma unroll
    for (int q = 0; q < (KCP*256)/(256*4); q++)   // 4 chunks
        cp_async16(d + q*256*16, g + q*256);
    cp_commit();
}

// core f32x2 micro-GEMM over one panel: acc[i][j] over rows rbase..rbase+R-1
template <int R>
__device__ __forceinline__ void compute_panel16(const float* __restrict__ pan,
    const float* __restrict__ A, int k0, ull acc[R][4], int rbase, int ct)
{
#pragma unroll
    for (int kk = 0; kk < KCP; kk++) {
        const float* bp = pan + kk*256 + 2*ct;
        ull b0 = *(const ull*)(bp);
        ull b1 = *(const ull*)(bp + 64);
        ull b2 = *(const ull*)(bp + 128);
        ull b3 = *(const ull*)(bp + 192);
#pragma unroll
        for (int i = 0; i < R; i++) {
            ull a2 = splat2(A[(rbase + i)*256 + k0 + kk]);
            ffma2(acc[i][0], a2, b0);
            ffma2(acc[i][1], a2, b1);
            ffma2(acc[i][2], a2, b2);
            ffma2(acc[i][3], a2, b3);
        }
    }
}

// ---------------- generic scalar GEMM (small-K / odd-K cases) ----------------
__global__ void __launch_bounds__(256) gemm256(
    const float* __restrict__ A, int lda, int rows, int K,
    const float* __restrict__ B, int ldb,
    const float* __restrict__ bias,
    float* __restrict__ C, int act)
{
    extern __shared__ float sm[];
    float* sA    = sm;                 // BM*KC
    float* sB    = sm + BM*KC;         // KC*257
    float* sBias = sB + KC*257;        // 256

    int tid = threadIdx.x;
    int rt = tid >> 5, ct = tid & 31;
    long r0 = (long)blockIdx.x * BM;

    sBias[tid] = bias ? bias[tid] : 0.f;

    float acc[8][8];
#pragma unroll
    for (int i = 0; i < 8; i++)
#pragma unroll
        for (int j = 0; j < 8; j++) acc[i][j] = 0.f;

    for (int k0 = 0; k0 < K; k0 += KC) {
#pragma unroll 4
        for (int t = tid; t < BM*KC; t += 256) {
            int row = t >> 6, kk = t & 63;
            int k = k0 + kk;
            long r = r0 + row;
            sA[t] = (k < K && r < rows) ? A[r*(long)lda + k] : 0.f;
        }
#pragma unroll 8
        for (int t = tid; t < 256*KC; t += 256) {
            int n = t >> 6, kk = t & 63;
            int k = k0 + kk;
            sB[kk*257 + n] = (k < K) ? B[(long)n*ldb + k] : 0.f;
        }
        __syncthreads();
#pragma unroll 8
        for (int kk = 0; kk < KC; kk++) {
            float a[8], bv[8];
#pragma unroll
            for (int i = 0; i < 8; i++) a[i] = sA[(rt*8 + i)*KC + kk];
#pragma unroll
            for (int j = 0; j < 8; j++) bv[j] = sB[kk*257 + ct + j*32];
#pragma unroll
            for (int i = 0; i < 8; i++)
#pragma unroll
                for (int j = 0; j < 8; j++) acc[i][j] = fmaf(a[i], bv[j], acc[i][j]);
        }
        __syncthreads();
    }
#pragma unroll
    for (int i = 0; i < 8; i++) {
        long row = r0 + rt*8 + i;
        if (row < rows) {
#pragma unroll
            for (int j = 0; j < 8; j++) {
                int col = ct + j*32;
                float v = acc[i][j] + sBias[col];
                if (act == 1) v = fmaxf(v, 0.f);
                C[row*256 + col] = v;
            }
        }
    }
}

// ---------------- f32x2 GEMM, K=256, N=256, Bt pre-transposed (k-major) ----------------
__global__ void __launch_bounds__(256,2) gemm_ffma2(
    const float* __restrict__ A,      // [rows][256]
    const float* __restrict__ Bt,     // [256][256] k-major
    const float* __restrict__ bias,
    float* __restrict__ C, int act)
{
    extern __shared__ float sm[];
    float* sA    = sm;                // 64*256 = 16384
    float* sPan  = sA + 64*256;       // 3*KCP*256 = 12288
    float* sBias = sPan + 3*KCP*256;  // 256

    int tid = threadIdx.x;
    int warp = tid >> 5, ct = tid & 31;
    int rbase = warp * 8;
    long r0 = (long)blockIdx.x * 64;

    sBias[tid] = bias ? bias[tid] : 0.f;
    // load A tile (coalesced float4)
    {
        const float4* g4 = (const float4*)(A + r0*256);
        float4* s4 = (float4*)sA;
#pragma unroll 4
        for (int i = tid; i < 64*64; i += 256) s4[i] = g4[i];
    }
    issue_panel(Bt + 0*KCP*256, sPan + 0*KCP*256, tid);
    issue_panel(Bt + 1*KCP*256, sPan + 1*KCP*256, tid);

    ull acc[8][4];
#pragma unroll
    for (int i = 0; i < 8; i++)
#pragma unroll
        for (int j = 0; j < 4; j++) acc[i][j] = 0ull;

    for (int p = 0; p < 16; p++) {
        if (p < 15) cp_wait<1>(); else cp_wait<0>();
        __syncthreads();
        if (p + 2 < 16)
            issue_panel(Bt + (p+2)*KCP*256, sPan + ((p+2)%3)*KCP*256, tid);
        compute_panel16<8>(sPan + (p%3)*KCP*256, sA, p*KCP, acc, rbase, ct);
    }

#pragma unroll
    for (int i = 0; i < 8; i++) {
        long row = r0 + rbase + i;
#pragma unroll
        for (int j = 0; j < 4; j++) {
            int col = 2*(ct + 32*j);
            float2 v = unpack2(acc[i][j]);
            v.x += sBias[col];
            v.y += sBias[col+1];
            if (act) { v.x = fmaxf(v.x, 0.f); v.y = fmaxf(v.y, 0.f); }
            *(float2*)(C + row*256 + col) = v;
        }
    }
}

// ---------------- 256x256 transpose: out[k][256+n] = in[n][ldin+k] ----------------
__global__ void transpose256(const float* __restrict__ in, int ldin, float* __restrict__ out)
{
    __shared__ float tl[32][33];
    int bx = blockIdx.x*32, by = blockIdx.y*32;  // bx: k, by: n
    int tx = threadIdx.x, ty = threadIdx.y;      // block(32,8)
#pragma unroll
    for (int r = 0; r < 4; r++)
        tl[ty + 8*r][tx] = in[(long)(by + ty + 8*r)*ldin + bx + tx];
    __syncthreads();
#pragma unroll
    for (int r = 0; r < 4; r++)
        out[(long)(bx + ty + 8*r)*256 + by + tx] = tl[tx][ty + 8*r];
}

// ---------------- gateE = mi @ embed^T  (SB x 20) ----------------
__global__ void __launch_bounds__(256) gatee_kernel(
    const float* __restrict__ mi, const float* __restrict__ embed, float* __restrict__ out)
{
    extern __shared__ float sm[];
    float* sMi = sm;            // 64*256
    float* sE  = sm + 64*256;   // 20*256
    int tid = threadIdx.x, ct = tid & 31;
    long r0 = (long)blockIdx.x * 64;
    {
        const float4* g4 = (const float4*)(mi + r0*256);
        float4* s4 = (float4*)sMi;
#pragma unroll 4
        for (int i = tid; i < 64*64; i += 256) s4[i] = g4[i];
        const float4* e4 = (const float4*)embed;
        float4* se4 = (float4*)sE;
        for (int i = tid; i < 20*64; i += 256) se4[i] = e4[i];
    }
    __syncthreads();
#pragma unroll
    for (int q = 0; q < 5; q++) {
        int o = q*256 + tid;            // 0..1279
        int row = o / 20, m = o % 20;
        float acc = 0.f;
#pragma unroll 8
        for (int k = 0; k < 256; k++) {
            int kr = (k + ct*8) & 255;  // rotate to avoid bank conflicts
            acc += sMi[row*256 + kr] * sE[m*256 + kr];
        }
        out[r0*20 + o] = acc;
    }
}

// ---------------- fused persistent scan (state SMEM-resident, weights cp.async) ----------------
__global__ void __launch_bounds__(256,1) scan_kernel(
    const float* __restrict__ Ut, const float* __restrict__ J1t,
    const float* __restrict__ U_b, const float* __restrict__ J_b,
    const float* __restrict__ prelu_a,
    const float* __restrict__ mi, const float* __restrict__ sentJ,
    const float* __restrict__ gateE, const float* __restrict__ keyJ,
    float* __restrict__ mem)
{
    extern __shared__ float sm[];
    float* sMem  = sm;                       // 80*256 = 20480
    float* sA1   = sMem + TROWS*256;         // 20480
    float* sPan  = sA1  + TROWS*256;         // 3*16*256 = 12288
    float* sSent = sPan + 3*KCP*256;         // 4*256
    float* sSJ   = sSent + 4*256;            // 4*256
    float* sUb   = sSJ   + 4*256;            // 256
    float* sJb   = sUb   + 256;              // 256

    int tid = threadIdx.x;
    int warp = tid >> 5, ct = tid & 31;
    int rbase = warp * RPT;
    float alpha = prelu_a[0];
    sUb[tid] = U_b[tid];
    sJb[tid] = J_b[tid];

    int t0 = (blockIdx.x     * NTILES) / SCAN_GRID;
    int t1 = ((blockIdx.x+1) * NTILES) / SCAN_GRID;

    for (int t = t0; t < t1; t++) {
        int r0 = t * TROWS;
        int b0 = t * 4;                       // 4 batches per tile exactly
        __syncthreads();                      // prev tile fully done
        {
            const float4* g4 = (const float4*)(mem + (size_t)r0*256);
            float4* s4 = (float4*)sMem;
#pragma unroll 4
            for (int i = tid; i < TROWS*64; i += 256) s4[i] = g4[i];
        }

        for (int s = 0; s < SEQ; s++) {
            __syncthreads();                  // prev epilogue done (sSJ), sMem tile loaded
            {
                const float4* g1 = (const float4*)(mi    + ((size_t)s*BSZ + b0)*256);
                const float4* g2 = (const float4*)(sentJ + ((size_t)s*BSZ + b0)*256);
                ((float4*)sSent)[tid] = g1[tid];   // 256 float4 = 4 batches
                ((float4*)sSJ)[tid]   = g2[tid];
            }
            // warm the panel pipeline (buffers 0,1 free by loop-barrier argument)
            issue_panel(Ut + 0*KCP*256, sPan + 0*KCP*256, tid);
            issue_panel(Ut + 1*KCP*256, sPan + 1*KCP*256, tid);
            __syncthreads();                  // sSent/sSJ visible

            // ---- gate (sent.mem in SMEM + precomputed sent.embed) ----
            float gv[RPT];
#pragma unroll
            for (int i = 0; i < RPT; i++) {
                int lr = rbase + i;
                const float* se = sSent + (lr/20)*256;
                float p = 0.f;
#pragma unroll
                for (int q = 0; q < 8; q++) {
                    int k = ct + q*32;
                    p += se[k] * sMem[lr*256 + k];
                }
#pragma unroll
                for (int o = 16; o > 0; o >>= 1) p += __shfl_xor_sync(0xffffffffu, p, o);
                p += gateE[(size_t)s*ROWS + r0 + lr];
                gv[i] = 1.f / (1.f + expf(-p));
            }

            ull acc[RPT][4];
#pragma unroll
            for (int i = 0; i < RPT; i++)
#pragma unroll
                for (int j = 0; j < 4; j++) acc[i][j] = 0ull;

            // ---- 32 panels: 16 of U (GEMM1 on sMem), 16 of J1 (GEMM2 on sA1) ----
            for (int p = 0; p < NPAN; p++) {
                if (p < NPAN-1) cp_wait<1>(); else cp_wait<0>();
                __syncthreads();
                int pn = p + 2;
                if (pn < NPAN) {
                    const float* src = (pn < 16) ? (Ut + pn*KCP*256)
                                                 : (J1t + (pn-16)*KCP*256);
                    issue_panel(src, sPan + (pn%3)*KCP*256, tid);
                }
                const float* A = (p < 16) ? sMem : sA1;
                compute_panel16<RPT>(sPan + (p%3)*KCP*256, A, (p & 15)*KCP, acc, rbase, ct);

                if (p == 15) {
                    // A1 = relu(acc + U_b), then reset acc for GEMM2
#pragma unroll
                    for (int i = 0; i < RPT; i++) {
#pragma unroll
                        for (int j = 0; j < 4; j++) {
                            int col = 2*(ct + 32*j);
                            float2 v = unpack2(acc[i][j]);
                            v.x = fmaxf(v.x + sUb[col],   0.f);
                            v.y = fmaxf(v.y + sUb[col+1], 0.f);
                            *(float2*)(sA1 + (rbase+i)*256 + col) = v;
                            acc[i][j] = 0ull;
                        }
                    }
                }
            }

            // ---- epilogue: prelu, gated update, normalize; sMem in place (warp-local) ----
#pragma unroll
            for (int i = 0; i < RPT; i++) {
                int lr = rbase + i;
                int m  = lr % MSLOT;
                float g = gv[i];
                const float* sj = sSJ + (lr/20)*256;
                const float* kj = keyJ + m*256;
                float u[8];
                float ss = 0.f;
#pragma unroll
                for (int j = 0; j < 4; j++) {
                    int col = 2*(ct + 32*j);
                    float2 c = unpack2(acc[i][j]);
                    float2 kv = *(const float2*)(kj + col);
                    float c0 = c.x + sJb[col]   + sj[col]   + kv.x;
                    float c1 = c.y + sJb[col+1] + sj[col+1] + kv.y;
                    c0 = c0 > 0.f ? c0 : alpha * c0;
                    c1 = c1 > 0.f ? c1 : alpha * c1;
                    float u0 = sMem[lr*256 + col]     + g * c0;
                    float u1 = sMem[lr*256 + col + 1] + g * c1;
                    u[2*j] = u0; u[2*j+1] = u1;
                    ss += u0*u0 + u1*u1;
                }
#pragma unroll
                for (int o = 16; o > 0; o >>= 1) ss += __shfl_xor_sync(0xffffffffu, ss, o);
                float inv = 1.f / (sqrtf(ss) + 1e-12f);
#pragma unroll
                for (int j = 0; j < 4; j++) {
                    int col = 2*(ct + 32*j);
                    float2 w; w.x = u[2*j]*inv; w.y = u[2*j+1]*inv;
                    *(float2*)(sMem + lr*256 + col) = w;
                }
            }
        }

        __syncthreads();
        {
            const float4* s4 = (const float4*)sMem;
            float4* g4 = (float4*)(mem + (size_t)r0*256);
#pragma unroll 4
            for (int i = tid; i < TROWS*64; i += 256) g4[i] = s4[i];
        }
    }
}

// ---------------- memories init: mem[b*20+m][d] = embed[m][d] ----------------
__global__ void init_mem_kernel(const float* __restrict__ embed, float* __restrict__ mem)
{
    long idx = (long)blockIdx.x * 256 + threadIdx.x;
    int d = idx & 255;
    long rm = idx >> 8;
    int m = (int)(rm % MSLOT);
    mem[idx] = embed[m*256 + d];
}

// ---------------- attention + concat ----------------
__global__ void __launch_bounds__(256) attn_kernel(
    const float* __restrict__ mem, const float* __restrict__ q, float* __restrict__ cat)
{
    __shared__ float sQ[256];
    __shared__ float sM[MSLOT*256];
    __shared__ float sE[MSLOT];
    int b = blockIdx.x, tid = threadIdx.x;
    sQ[tid] = q[(long)b*256 + tid];
    for (int t = tid; t < MSLOT*256; t += 256) sM[t] = mem[(long)b*MSLOT*256 + t];
    __syncthreads();
    int w = tid >> 5, l = tid & 31;
    for (int m = w; m < MSLOT; m += 8) {
        float p = 0.f;
        for (int k = l; k < 256; k += 32) p += sM[m*256 + k] * sQ[k];
#pragma unroll
        for (int o = 16; o > 0; o >>= 1) p += __shfl_xor_sync(0xffffffffu, p, o);
        if (l == 0) sE[m] = p;
    }
    __syncthreads();
    float mx = -1e30f;
    for (int m = 0; m < MSLOT; m++) mx = fmaxf(mx, sE[m]);
    float sum = 0.f;
    for (int m = 0; m < MSLOT; m++) sum += expf(sE[m] - mx);
    float att = 0.f;
    for (int m = 0; m < MSLOT; m++) att += sM[m*256 + tid] * expf(sE[m] - mx);
    att /= sum;
    cat[(long)b*512 + tid]       = sQ[tid];
    cat[(long)b*512 + 256 + tid] = att;
}

// ---------------- host launcher ----------------
extern "C" void kernel_launch(void* const* d_in, const int* in_sizes, int n_in,
                              void* d_out, int out_size)
{
    const float* memory_inputs = (const float*)d_in[0];
    const float* question      = (const float*)d_in[1];
    const float* C_w = (const float*)d_in[2];
    const float* C_b = (const float*)d_in[3];
    const float* Q_w = (const float*)d_in[4];
    const float* Q_b = (const float*)d_in[5];
    const float* H_w = (const float*)d_in[6];
    const float* H_b = (const float*)d_in[7];
    const float* U_w = (const float*)d_in[8];
    const float* U_b = (const float*)d_in[9];
    const float* V_w = (const float*)d_in[10];
    const float* V_b = (const float*)d_in[11];
    const float* W_w = (const float*)d_in[12];
    const float* W_b = (const float*)d_in[13];
    const float* J_w = (const float*)d_in[14];
    const float* J_b = (const float*)d_in[15];
    const float* prelu_a = (const float*)d_in[16];
    const float* embed   = (const float*)d_in[17];
    float* out = (float*)d_out;

    size_t gemm_smem  = (size_t)(BM*KC + KC*257 + 256) * sizeof(float);
    size_t gx2_smem   = (size_t)(64*256 + 3*KCP*256 + 256) * sizeof(float);
    size_t scan_smem  = (size_t)(TROWS*256*2 + 3*KCP*256 + 4*256*2 + 512) * sizeof(float);
    size_t gatee_smem = (size_t)(64*256 + 20*256) * sizeof(float);
    cudaFuncSetAttribute(gemm256,      cudaFuncAttributeMaxDynamicSharedMemorySize, (int)gemm_smem);
    cudaFuncSetAttribute(gemm_ffma2,   cudaFuncAttributeMaxDynamicSharedMemorySize, (int)gx2_smem);
    cudaFuncSetAttribute(scan_kernel,  cudaFuncAttributeMaxDynamicSharedMemorySize, (int)scan_smem);
    cudaFuncSetAttribute(gatee_kernel, cudaFuncAttributeMaxDynamicSharedMemorySize, (int)gatee_smem);

    float *mi, *tmp, *sentJ, *memb, *q, *a3, *keyJ, *cat, *gateE, *wT;
    cudaGetSymbolAddress((void**)&mi,    g_mi);
    cudaGetSymbolAddress((void**)&tmp,   g_tmp);
    cudaGetSymbolAddress((void**)&sentJ, g_sentJ);
    cudaGetSymbolAddress((void**)&memb,  g_mem);
    cudaGetSymbolAddress((void**)&q,     g_q);
    cudaGetSymbolAddress((void**)&a3,    g_a3);
    cudaGetSymbolAddress((void**)&keyJ,  g_keyJ);
    cudaGetSymbolAddress((void**)&cat,   g_cat);
    cudaGetSymbolAddress((void**)&gateE, g_gateE);
    cudaGetSymbolAddress((void**)&wT,    g_wT);
    float* Ut  = wT;
    float* J1t = wT + (size_t)HID*HID;
    float* Vt  = wT + 2*(size_t)HID*HID;
    float* J2t = wT + 3*(size_t)HID*HID;

    // weight transposes (one-time, tiny)
    dim3 tb(32, 8), tg(8, 8);
    transpose256<<<tg, tb>>>(U_w, 256, Ut);
    transpose256<<<tg, tb>>>(J_w, 768, J1t);
    transpose256<<<tg, tb>>>(V_w, 256, Vt);
    transpose256<<<tg, tb>>>(J_w + 256, 768, J2t);

    // init recurrent state
    init_mem_kernel<<<ROWS, 256>>>(embed, memb);

    // precompute
    gemm256<<<SB/BM, 256, gemm_smem>>>(memory_inputs, DIN, SB, DIN, C_w, DIN, C_b, mi, 1);
    gemm256<<<BSZ/BM, 256, gemm_smem>>>(question, QDIM, BSZ, QDIM, Q_w, QDIM, Q_b, q, 1);
    gatee_kernel<<<SB/64, 256, gatee_smem>>>(mi, embed, gateE);
    gemm_ffma2<<<SB/64, 256, gx2_smem>>>(mi, Vt, V_b, tmp, 1);
    gemm_ffma2<<<SB/64, 256, gx2_smem>>>(tmp, J2t, (const float*)0, sentJ, 0);
    gemm256<<<1, 256, gemm_smem>>>(embed, HID, MSLOT, HID, W_w, HID, W_b, a3, 1);
    gemm256<<<1, 256, gemm_smem>>>(a3, HID, MSLOT, HID, J_w + 512, 768, (const float*)0, keyJ, 0);

    // fused persistent scan
    scan_kernel<<<SCAN_GRID, 256, scan_smem>>>(Ut, J1t, U_b, J_b, prelu_a,
                                               mi, sentJ, gateE, keyJ, memb);

    // attention + concat, then final projection
    attn_kernel<<<BSZ, 256>>>(memb, q, cat);
    gemm256<<<BSZ/BM, 256, gemm_smem>>>(cat, 2*HID, BSZ, 2*HID, H_w, 2*HID, H_b, out, 1);
}

// round 7
// speedup vs baseline: 1.4670x; 1.0009x over previous
#include <cuda_runtime.h>

#define SEQ   128
#define BSZ   1024
#define DIN   37
#define QDIM  11
#define HID   256
#define MSLOT 20
#define ROWS  (BSZ*MSLOT)   // 20480
#define SB    (SEQ*BSZ)     // 131072

#define BM 64
#define KC 64

// fused-scan tiling
#define TROWS 80                 // rows per tile = 4 batches exactly
#define RPT   10                 // rows per thread (8 warps x 10 = 80)
#define KCP   16                 // panel K depth
#define NPAN  32                 // panels per step (16 U + 16 J1)
#define NTILES (ROWS/TROWS)      // 256
#define SCAN_GRID 148

typedef unsigned long long ull;

// ---------------- scratch (no cudaMalloc allowed) ----------------
__device__ float g_mi[(size_t)SB*HID];
__device__ float g_tmp[(size_t)SB*HID];
__device__ float g_sentJ[(size_t)SB*HID];
__device__ float g_mem[(size_t)ROWS*HID];
__device__ float g_q[(size_t)BSZ*HID];
__device__ float g_a3[(size_t)MSLOT*HID];
__device__ float g_keyJ[(size_t)MSLOT*HID];
__device__ float g_cat[(size_t)BSZ*2*HID];
__device__ float g_gateE[(size_t)SB*MSLOT];          // sent . embed per (s,b,m)
__device__ float g_wT[4*(size_t)HID*HID];            // Ut, J1t, Vt, J2t (k-major)

// ---------------- f32x2 / cp.async helpers ----------------
__device__ __forceinline__ ull splat2(float a) {
    ull r; asm("mov.b64 %0, {%1, %1};" : "=l"(r) : "f"(a)); return r;
}
__device__ __forceinline__ void ffma2(ull& acc, ull a, ull b) {
    asm("fma.rn.f32x2 %0, %1, %2, %0;" : "+l"(acc) : "l"(a), "l"(b));
}
__device__ __forceinline__ float2 unpack2(ull v) {
    float2 f; asm("mov.b64 {%0, %1}, %2;" : "=f"(f.x), "=f"(f.y) : "l"(v)); return f;
}
__device__ __forceinline__ unsigned smem_u32(const void* p) {
    unsigned r;
    asm("{ .reg .u64 t; cvta.to.shared.u64 t, %1; cvt.u32.u64 %0, t; }" : "=r"(r) : "l"(p));
    return r;
}
__device__ __forceinline__ void cp_async16(unsigned saddr, const void* gptr) {
    asm volatile("cp.async.cg.shared.global [%0], [%1], 16;" :: "r"(saddr), "l"(gptr));
}
__device__ __forceinline__ void cp_commit() {
    asm volatile("cp.async.commit_group;");
}
template <int N>
__device__ __forceinline__ void cp_wait() {
    asm volatile("cp.async.wait_group %0;" :: "n"(N));
}

// issue one KCP x 256 panel (float4 copies, conflict-free)
__device__ __forceinline__ void issue_panel(const float* __restrict__ src,
                                            float* __restrict__ dst, int tid)
{
    unsigned d = smem_u32(dst) + (unsigned)tid * 16u;
    const float4* g = (const float4*)src + tid;
#pragma unroll
    for (int q = 0; q < (KCP*256)/(256*4); q++)   // 4 chunks
        cp_async16(d + q*256*16, g + q*256);
    cp_commit();
}

// core f32x2 micro-GEMM over one panel: acc[i][j] over rows rbase..rbase+R-1
template <int R>
__device__ __forceinline__ void compute_panel16(const float* __restrict__ pan,
    const float* __restrict__ A, int k0, ull acc[R][4], int rbase, int ct)
{
#pragma unroll
    for (int kk = 0; kk < KCP; kk++) {
        const float* bp = pan + kk*256 + 2*ct;
        ull b0 = *(const ull*)(bp);
        ull b1 = *(const ull*)(bp + 64);
        ull b2 = *(const ull*)(bp + 128);
        ull b3 = *(const ull*)(bp + 192);
#pragma unroll
        for (int i = 0; i < R; i++) {
            ull a2 = splat2(A[(rbase + i)*256 + k0 + kk]);
            ffma2(acc[i][0], a2, b0);
            ffma2(acc[i][1], a2, b1);
            ffma2(acc[i][2], a2, b2);
            ffma2(acc[i][3], a2, b3);
        }
    }
}

// ---------------- generic scalar GEMM (small-K / odd-K cases) ----------------
__global__ void __launch_bounds__(256) gemm256(
    const float* __restrict__ A, int lda, int rows, int K,
    const float* __restrict__ B, int ldb,
    const float* __restrict__ bias,
    float* __restrict__ C, int act)
{
    extern __shared__ float sm[];
    float* sA    = sm;                 // BM*KC
    float* sB    = sm + BM*KC;         // KC*257
    float* sBias = sB + KC*257;        // 256

    int tid = threadIdx.x;
    int rt = tid >> 5, ct = tid & 31;
    long r0 = (long)blockIdx.x * BM;

    sBias[tid] = bias ? bias[tid] : 0.f;

    float acc[8][8];
#pragma unroll
    for (int i = 0; i < 8; i++)
#pragma unroll
        for (int j = 0; j < 8; j++) acc[i][j] = 0.f;

    for (int k0 = 0; k0 < K; k0 += KC) {
#pragma unroll 4
        for (int t = tid; t < BM*KC; t += 256) {
            int row = t >> 6, kk = t & 63;
            int k = k0 + kk;
            long r = r0 + row;
            sA[t] = (k < K && r < rows) ? A[r*(long)lda + k] : 0.f;
        }
#pragma unroll 8
        for (int t = tid; t < 256*KC; t += 256) {
            int n = t >> 6, kk = t & 63;
            int k = k0 + kk;
            sB[kk*257 + n] = (k < K) ? B[(long)n*ldb + k] : 0.f;
        }
        __syncthreads();
#pragma unroll 8
        for (int kk = 0; kk < KC; kk++) {
            float a[8], bv[8];
#pragma unroll
            for (int i = 0; i < 8; i++) a[i] = sA[(rt*8 + i)*KC + kk];
#pragma unroll
            for (int j = 0; j < 8; j++) bv[j] = sB[kk*257 + ct + j*32];
#pragma unroll
            for (int i = 0; i < 8; i++)
#pragma unroll
                for (int j = 0; j < 8; j++) acc[i][j] = fmaf(a[i], bv[j], acc[i][j]);
        }
        __syncthreads();
    }
#pragma unroll
    for (int i = 0; i < 8; i++) {
        long row = r0 + rt*8 + i;
        if (row < rows) {
#pragma unroll
            for (int j = 0; j < 8; j++) {
                int col = ct + j*32;
                float v = acc[i][j] + sBias[col];
                if (act == 1) v = fmaxf(v, 0.f);
                C[row*256 + col] = v;
            }
        }
    }
}

// ---------------- f32x2 GEMM, K=256, N=256, Bt pre-transposed (k-major) ----------------
__global__ void __launch_bounds__(256,2) gemm_ffma2(
    const float* __restrict__ A,      // [rows][256]
    const float* __restrict__ Bt,     // [256][256] k-major
    const float* __restrict__ bias,
    float* __restrict__ C, int act)
{
    extern __shared__ float sm[];
    float* sA    = sm;                // 64*256 = 16384
    float* sPan  = sA + 64*256;       // 3*KCP*256 = 12288
    float* sBias = sPan + 3*KCP*256;  // 256

    int tid = threadIdx.x;
    int warp = tid >> 5, ct = tid & 31;
    int rbase = warp * 8;
    long r0 = (long)blockIdx.x * 64;

    sBias[tid] = bias ? bias[tid] : 0.f;
    // load A tile (coalesced float4)
    {
        const float4* g4 = (const float4*)(A + r0*256);
        float4* s4 = (float4*)sA;
#pragma unroll 4
        for (int i = tid; i < 64*64; i += 256) s4[i] = g4[i];
    }
    issue_panel(Bt + 0*KCP*256, sPan + 0*KCP*256, tid);
    issue_panel(Bt + 1*KCP*256, sPan + 1*KCP*256, tid);

    ull acc[8][4];
#pragma unroll
    for (int i = 0; i < 8; i++)
#pragma unroll
        for (int j = 0; j < 4; j++) acc[i][j] = 0ull;

    for (int p = 0; p < 16; p++) {
        if (p < 15) cp_wait<1>(); else cp_wait<0>();
        __syncthreads();
        if (p + 2 < 16)
            issue_panel(Bt + (p+2)*KCP*256, sPan + ((p+2)%3)*KCP*256, tid);
        compute_panel16<8>(sPan + (p%3)*KCP*256, sA, p*KCP, acc, rbase, ct);
    }

#pragma unroll
    for (int i = 0; i < 8; i++) {
        long row = r0 + rbase + i;
#pragma unroll
        for (int j = 0; j < 4; j++) {
            int col = 2*(ct + 32*j);
            float2 v = unpack2(acc[i][j]);
            v.x += sBias[col];
            v.y += sBias[col+1];
            if (act) { v.x = fmaxf(v.x, 0.f); v.y = fmaxf(v.y, 0.f); }
            *(float2*)(C + row*256 + col) = v;
        }
    }
}

// ---------------- 256x256 transpose: out[k][256+n] = in[n][ldin+k] ----------------
__global__ void transpose256(const float* __restrict__ in, int ldin, float* __restrict__ out)
{
    __shared__ float tl[32][33];
    int bx = blockIdx.x*32, by = blockIdx.y*32;  // bx: k, by: n
    int tx = threadIdx.x, ty = threadIdx.y;      // block(32,8)
#pragma unroll
    for (int r = 0; r < 4; r++)
        tl[ty + 8*r][tx] = in[(long)(by + ty + 8*r)*ldin + bx + tx];
    __syncthreads();
#pragma unroll
    for (int r = 0; r < 4; r++)
        out[(long)(bx + ty + 8*r)*256 + by + tx] = tl[tx][ty + 8*r];
}

// ---------------- gateE = mi @ embed^T  (SB x 20) ----------------
__global__ void __launch_bounds__(256) gatee_kernel(
    const float* __restrict__ mi, const float* __restrict__ embed, float* __restrict__ out)
{
    extern __shared__ float sm[];
    float* sMi = sm;            // 64*256
    float* sE  = sm + 64*256;   // 20*256
    int tid = threadIdx.x, ct = tid & 31;
    long r0 = (long)blockIdx.x * 64;
    {
        const float4* g4 = (const float4*)(mi + r0*256);
        float4* s4 = (float4*)sMi;
#pragma unroll 4
        for (int i = tid; i < 64*64; i += 256) s4[i] = g4[i];
        const float4* e4 = (const float4*)embed;
        float4* se4 = (float4*)sE;
        for (int i = tid; i < 20*64; i += 256) se4[i] = e4[i];
    }
    __syncthreads();
#pragma unroll
    for (int q = 0; q < 5; q++) {
        int o = q*256 + tid;            // 0..1279
        int row = o / 20, m = o % 20;
        float acc = 0.f;
#pragma unroll 8
        for (int k = 0; k < 256; k++) {
            int kr = (k + ct*8) & 255;  // rotate to avoid bank conflicts
            acc += sMi[row*256 + kr] * sE[m*256 + kr];
        }
        out[r0*20 + o] = acc;
    }
}

// ---------------- fused persistent scan (state SMEM-resident, weights cp.async) ----------------
__global__ void __launch_bounds__(256,1) scan_kernel(
    const float* __restrict__ Ut, const float* __restrict__ J1t,
    const float* __restrict__ U_b, const float* __restrict__ J_b,
    const float* __restrict__ prelu_a,
    const float* __restrict__ mi, const float* __restrict__ sentJ,
    const float* __restrict__ gateE, const float* __restrict__ keyJ,
    float* __restrict__ mem)
{
    extern __shared__ float sm[];
    float* sMem  = sm;                       // 80*256 = 20480
    float* sA1   = sMem + TROWS*256;         // 20480
    float* sPan  = sA1  + TROWS*256;         // 3*16*256 = 12288
    float* sSent = sPan + 3*KCP*256;         // 4*256
    float* sSJ   = sSent + 4*256;            // 4*256
    float* sUb   = sSJ   + 4*256;            // 256
    float* sJb   = sUb   + 256;              // 256

    int tid = threadIdx.x;
    int warp = tid >> 5, ct = tid & 31;
    int rbase = warp * RPT;
    float alpha = prelu_a[0];
    sUb[tid] = U_b[tid];
    sJb[tid] = J_b[tid];

    int t0 = (blockIdx.x     * NTILES) / SCAN_GRID;
    int t1 = ((blockIdx.x+1) * NTILES) / SCAN_GRID;

    for (int t = t0; t < t1; t++) {
        int r0 = t * TROWS;
        int b0 = t * 4;                       // 4 batches per tile exactly
        __syncthreads();                      // prev tile fully done
        {
            const float4* g4 = (const float4*)(mem + (size_t)r0*256);
            float4* s4 = (float4*)sMem;
#pragma unroll 4
            for (int i = tid; i < TROWS*64; i += 256) s4[i] = g4[i];
        }

        for (int s = 0; s < SEQ; s++) {
            __syncthreads();                  // prev epilogue done (sSJ), sMem tile loaded
            {
                const float4* g1 = (const float4*)(mi    + ((size_t)s*BSZ + b0)*256);
                const float4* g2 = (const float4*)(sentJ + ((size_t)s*BSZ + b0)*256);
                ((float4*)sSent)[tid] = g1[tid];   // 256 float4 = 4 batches
                ((float4*)sSJ)[tid]   = g2[tid];
            }
            // warm the panel pipeline (buffers 0,1 free by loop-barrier argument)
            issue_panel(Ut + 0*KCP*256, sPan + 0*KCP*256, tid);
            issue_panel(Ut + 1*KCP*256, sPan + 1*KCP*256, tid);
            __syncthreads();                  // sSent/sSJ visible

            // ---- gate (sent.mem in SMEM + precomputed sent.embed) ----
            float gv[RPT];
#pragma unroll
            for (int i = 0; i < RPT; i++) {
                int lr = rbase + i;
                const float* se = sSent + (lr/20)*256;
                float p = 0.f;
#pragma unroll
                for (int q = 0; q < 8; q++) {
                    int k = ct + q*32;
                    p += se[k] * sMem[lr*256 + k];
                }
#pragma unroll
                for (int o = 16; o > 0; o >>= 1) p += __shfl_xor_sync(0xffffffffu, p, o);
                p += gateE[(size_t)s*ROWS + r0 + lr];
                gv[i] = 1.f / (1.f + expf(-p));
            }

            ull acc[RPT][4];
#pragma unroll
            for (int i = 0; i < RPT; i++)
#pragma unroll
                for (int j = 0; j < 4; j++) acc[i][j] = 0ull;

            // ---- 32 panels: 16 of U (GEMM1 on sMem), 16 of J1 (GEMM2 on sA1) ----
            for (int p = 0; p < NPAN; p++) {
                if (p < NPAN-1) cp_wait<1>(); else cp_wait<0>();
                __syncthreads();
                int pn = p + 2;
                if (pn < NPAN) {
                    const float* src = (pn < 16) ? (Ut + pn*KCP*256)
                                                 : (J1t + (pn-16)*KCP*256);
                    issue_panel(src, sPan + (pn%3)*KCP*256, tid);
                }
                const float* A = (p < 16) ? sMem : sA1;
                compute_panel16<RPT>(sPan + (p%3)*KCP*256, A, (p & 15)*KCP, acc, rbase, ct);

                if (p == 15) {
                    // A1 = relu(acc + U_b), then reset acc for GEMM2
#pragma unroll
                    for (int i = 0; i < RPT; i++) {
#pragma unroll
                        for (int j = 0; j < 4; j++) {
                            int col = 2*(ct + 32*j);
                            float2 v = unpack2(acc[i][j]);
                            v.x = fmaxf(v.x + sUb[col],   0.f);
                            v.y = fmaxf(v.y + sUb[col+1], 0.f);
                            *(float2*)(sA1 + (rbase+i)*256 + col) = v;
                            acc[i][j] = 0ull;
                        }
                    }
                }
            }

            // ---- epilogue: prelu, gated update, normalize; sMem in place (warp-local) ----
#pragma unroll
            for (int i = 0; i < RPT; i++) {
                int lr = rbase + i;
                int m  = lr % MSLOT;
                float g = gv[i];
                const float* sj = sSJ + (lr/20)*256;
                const float* kj = keyJ + m*256;
                float u[8];
                float ss = 0.f;
#pragma unroll
                for (int j = 0; j < 4; j++) {
                    int col = 2*(ct + 32*j);
                    float2 c = unpack2(acc[i][j]);
                    float2 kv = *(const float2*)(kj + col);
                    float c0 = c.x + sJb[col]   + sj[col]   + kv.x;
                    float c1 = c.y + sJb[col+1] + sj[col+1] + kv.y;
                    c0 = c0 > 0.f ? c0 : alpha * c0;
                    c1 = c1 > 0.f ? c1 : alpha * c1;
                    float u0 = sMem[lr*256 + col]     + g * c0;
                    float u1 = sMem[lr*256 + col + 1] + g * c1;
                    u[2*j] = u0; u[2*j+1] = u1;
                    ss += u0*u0 + u1*u1;
                }
#pragma unroll
                for (int o = 16; o > 0; o >>= 1) ss += __shfl_xor_sync(0xffffffffu, ss, o);
                float inv = 1.f / (sqrtf(ss) + 1e-12f);
#pragma unroll
                for (int j = 0; j < 4; j++) {
                    int col = 2*(ct + 32*j);
                    float2 w; w.x = u[2*j]*inv; w.y = u[2*j+1]*inv;
                    *(float2*)(sMem + lr*256 + col) = w;
                }
            }
        }

        __syncthreads();
        {
            const float4* s4 = (const float4*)sMem;
            float4* g4 = (float4*)(mem + (size_t)r0*256);
#pragma unroll 4
            for (int i = tid; i < TROWS*64; i += 256) g4[i] = s4[i];
        }
    }
}

// ---------------- memories init: mem[b*20+m][d] = embed[m][d] ----------------
__global__ void init_mem_kernel(const float* __restrict__ embed, float* __restrict__ mem)
{
    long idx = (long)blockIdx.x * 256 + threadIdx.x;
    int d = idx & 255;
    long rm = idx >> 8;
    int m = (int)(rm % MSLOT);
    mem[idx] = embed[m*256 + d];
}

// ---------------- attention + concat ----------------
__global__ void __launch_bounds__(256) attn_kernel(
    const float* __restrict__ mem, const float* __restrict__ q, float* __restrict__ cat)
{
    __shared__ float sQ[256];
    __shared__ float sM[MSLOT*256];
    __shared__ float sE[MSLOT];
    int b = blockIdx.x, tid = threadIdx.x;
    sQ[tid] = q[(long)b*256 + tid];
    for (int t = tid; t < MSLOT*256; t += 256) sM[t] = mem[(long)b*MSLOT*256 + t];
    __syncthreads();
    int w = tid >> 5, l = tid & 31;
    for (int m = w; m < MSLOT; m += 8) {
        float p = 0.f;
        for (int k = l; k < 256; k += 32) p += sM[m*256 + k] * sQ[k];
#pragma unroll
        for (int o = 16; o > 0; o >>= 1) p += __shfl_xor_sync(0xffffffffu, p, o);
        if (l == 0) sE[m] = p;
    }
    __syncthreads();
    float mx = -1e30f;
    for (int m = 0; m < MSLOT; m++) mx = fmaxf(mx, sE[m]);
    float sum = 0.f;
    for (int m = 0; m < MSLOT; m++) sum += expf(sE[m] - mx);
    float att = 0.f;
    for (int m = 0; m < MSLOT; m++) att += sM[m*256 + tid] * expf(sE[m] - mx);
    att /= sum;
    cat[(long)b*512 + tid]       = sQ[tid];
    cat[(long)b*512 + 256 + tid] = att;
}

// ---------------- host launcher ----------------
extern "C" void kernel_launch(void* const* d_in, const int* in_sizes, int n_in,
                              void* d_out, int out_size)
{
    const float* memory_inputs = (const float*)d_in[0];
    const float* question      = (const float*)d_in[1];
    const float* C_w = (const float*)d_in[2];
    const float* C_b = (const float*)d_in[3];
    const float* Q_w = (const float*)d_in[4];
    const float* Q_b = (const float*)d_in[5];
    const float* H_w = (const float*)d_in[6];
    const float* H_b = (const float*)d_in[7];
    const float* U_w = (const float*)d_in[8];
    const float* U_b = (const float*)d_in[9];
    const float* V_w = (const float*)d_in[10];
    const float* V_b = (const float*)d_in[11];
    const float* W_w = (const float*)d_in[12];
    const float* W_b = (const float*)d_in[13];
    const float* J_w = (const float*)d_in[14];
    const float* J_b = (const float*)d_in[15];
    const float* prelu_a = (const float*)d_in[16];
    const float* embed   = (const float*)d_in[17];
    float* out = (float*)d_out;

    size_t gemm_smem  = (size_t)(BM*KC + KC*257 + 256) * sizeof(float);
    size_t gx2_smem   = (size_t)(64*256 + 3*KCP*256 + 256) * sizeof(float);
    size_t scan_smem  = (size_t)(TROWS*256*2 + 3*KCP*256 + 4*256*2 + 512) * sizeof(float);
    size_t gatee_smem = (size_t)(64*256 + 20*256) * sizeof(float);
    cudaFuncSetAttribute(gemm256,      cudaFuncAttributeMaxDynamicSharedMemorySize, (int)gemm_smem);
    cudaFuncSetAttribute(gemm_ffma2,   cudaFuncAttributeMaxDynamicSharedMemorySize, (int)gx2_smem);
    cudaFuncSetAttribute(scan_kernel,  cudaFuncAttributeMaxDynamicSharedMemorySize, (int)scan_smem);
    cudaFuncSetAttribute(gatee_kernel, cudaFuncAttributeMaxDynamicSharedMemorySize, (int)gatee_smem);

    float *mi, *tmp, *sentJ, *memb, *q, *a3, *keyJ, *cat, *gateE, *wT;
    cudaGetSymbolAddress((void**)&mi,    g_mi);
    cudaGetSymbolAddress((void**)&tmp,   g_tmp);
    cudaGetSymbolAddress((void**)&sentJ, g_sentJ);
    cudaGetSymbolAddress((void**)&memb,  g_mem);
    cudaGetSymbolAddress((void**)&q,     g_q);
    cudaGetSymbolAddress((void**)&a3,    g_a3);
    cudaGetSymbolAddress((void**)&keyJ,  g_keyJ);
    cudaGetSymbolAddress((void**)&cat,   g_cat);
    cudaGetSymbolAddress((void**)&gateE, g_gateE);
    cudaGetSymbolAddress((void**)&wT,    g_wT);
    float* Ut  = wT;
    float* J1t = wT + (size_t)HID*HID;
    float* Vt  = wT + 2*(size_t)HID*HID;
    float* J2t = wT + 3*(size_t)HID*HID;

    // weight transposes (one-time, tiny)
    dim3 tb(32, 8), tg(8, 8);
    transpose256<<<tg, tb>>>(U_w, 256, Ut);
    transpose256<<<tg, tb>>>(J_w, 768, J1t);
    transpose256<<<tg, tb>>>(V_w, 256, Vt);
    transpose256<<<tg, tb>>>(J_w + 256, 768, J2t);

    // init recurrent state
    init_mem_kernel<<<ROWS, 256>>>(embed, memb);

    // precompute
    gemm256<<<SB/BM, 256, gemm_smem>>>(memory_inputs, DIN, SB, DIN, C_w, DIN, C_b, mi, 1);
    gemm256<<<BSZ/BM, 256, gemm_smem>>>(question, QDIM, BSZ, QDIM, Q_w, QDIM, Q_b, q, 1);
    gatee_kernel<<<SB/64, 256, gatee_smem>>>(mi, embed, gateE);
    gemm_ffma2<<<SB/64, 256, gx2_smem>>>(mi, Vt, V_b, tmp, 1);
    gemm_ffma2<<<SB/64, 256, gx2_smem>>>(tmp, J2t, (const float*)0, sentJ, 0);
    gemm256<<<1, 256, gemm_smem>>>(embed, HID, MSLOT, HID, W_w, HID, W_b, a3, 1);
    gemm256<<<1, 256, gemm_smem>>>(a3, HID, MSLOT, HID, J_w + 512, 768, (const float*)0, keyJ, 0);

    // fused persistent scan
    scan_kernel<<<SCAN_GRID, 256, scan_smem>>>(Ut, J1t, U_b, J_b, prelu_a,
                                               mi, sentJ, gateE, keyJ, memb);

    // attention + concat, then final projection
    attn_kernel<<<BSZ, 256>>>(memb, q, cat);
    gemm256<<<BSZ/BM, 256, gemm_smem>>>(cat, 2*HID, BSZ, 2*HID, H_w, 2*HID, H_b, out, 1);
}

// round 8
// speedup vs baseline: 1.4695x; 1.0017x over previous
#include <cuda_runtime.h>

#define SEQ   128
#define BSZ   1024
#define DIN   37
#define QDIM  11
#define HID   256
#define MSLOT 20
#define ROWS  (BSZ*MSLOT)   // 20480
#define SB    (SEQ*BSZ)     // 131072

#define BM 64
#define KC 64

// fused-scan tiling
#define TROWS 80                 // rows per tile = 4 batches exactly
#define RPT   10                 // rows per thread (8 warps x 10 = 80)
#define KCP   16                 // panel K depth
#define NPAN  32                 // panels per step (16 U + 16 J1)
#define NTILES (ROWS/TROWS)      // 256
#define SCAN_GRID 148

typedef unsigned long long ull;

// ---------------- scratch (no cudaMalloc allowed) ----------------
__device__ float g_mi[(size_t)SB*HID];
__device__ float g_tmp[(size_t)SB*HID];
__device__ float g_sentJ[(size_t)SB*HID];
__device__ float g_mem[(size_t)ROWS*HID];
__device__ float g_q[(size_t)BSZ*HID];
__device__ float g_a3[(size_t)MSLOT*HID];
__device__ float g_keyJ[(size_t)MSLOT*HID];
__device__ float g_cat[(size_t)BSZ*2*HID];
__device__ float g_gateE[(size_t)SB*MSLOT];          // sent . embed per (s,b,m)
__device__ float g_wT[4*(size_t)HID*HID];            // Ut, J1t, Vt, J2t (k-major)

// ---------------- f32x2 / cp.async helpers ----------------
__device__ __forceinline__ ull splat2(float a) {
    ull r; asm("mov.b64 %0, {%1, %1};" : "=l"(r) : "f"(a)); return r;
}
__device__ __forceinline__ void ffma2(ull& acc, ull a, ull b) {
    asm("fma.rn.f32x2 %0, %1, %2, %0;" : "+l"(acc) : "l"(a), "l"(b));
}
__device__ __forceinline__ float2 unpack2(ull v) {
    float2 f; asm("mov.b64 {%0, %1}, %2;" : "=f"(f.x), "=f"(f.y) : "l"(v)); return f;
}
__device__ __forceinline__ unsigned smem_u32(const void* p) {
    unsigned r;
    asm("{ .reg .u64 t; cvta.to.shared.u64 t, %1; cvt.u32.u64 %0, t; }" : "=r"(r) : "l"(p));
    return r;
}
__device__ __forceinline__ void cp_async16(unsigned saddr, const void* gptr) {
    asm volatile("cp.async.cg.shared.global [%0], [%1], 16;" :: "r"(saddr), "l"(gptr));
}
__device__ __forceinline__ void cp_commit() {
    asm volatile("cp.async.commit_group;");
}
template <int N>
__device__ __forceinline__ void cp_wait() {
    asm volatile("cp.async.wait_group %0;" :: "n"(N));
}

// issue one KCP x 256 panel (float4 copies, conflict-free)
__device__ __forceinline__ void issue_panel(const float* __restrict__ src,
                                            float* __restrict__ dst, int tid)
{
    unsigned d = smem_u32(dst) + (unsigned)tid * 16u;
    const float4* g = (const float4*)src + tid;
#pragma unroll
    for (int q = 0; q < (KCP*256)/(256*4); q++)   // 4 chunks
        cp_async16(d + q*256*16, g + q*256);
    cp_commit();
}

// core f32x2 micro-GEMM over one panel: acc[i][j] over rows rbase..rbase+R-1
template <int R>
__device__ __forceinline__ void compute_panel16(const float* __restrict__ pan,
    const float* __restrict__ A, int k0, ull acc[R][4], int rbase, int ct)
{
#pragma unroll
    for (int kk = 0; kk < KCP; kk++) {
        const float* bp = pan + kk*256 + 2*ct;
        ull b0 = *(const ull*)(bp);
        ull b1 = *(const ull*)(bp + 64);
        ull b2 = *(const ull*)(bp + 128);
        ull b3 = *(const ull*)(bp + 192);
#pragma unroll
        for (int i = 0; i < R; i++) {
            ull a2 = splat2(A[(rbase + i)*256 + k0 + kk]);
            ffma2(acc[i][0], a2, b0);
            ffma2(acc[i][1], a2, b1);
            ffma2(acc[i][2], a2, b2);
            ffma2(acc[i][3], a2, b3);
        }
    }
}

// ---------------- generic scalar GEMM (small-K / odd-K cases) ----------------
__global__ void __launch_bounds__(256) gemm256(
    const float* __restrict__ A, int lda, int rows, int K,
    const float* __restrict__ B, int ldb,
    const float* __restrict__ bias,
    float* __restrict__ C, int act)
{
    extern __shared__ float sm[];
    float* sA    = sm;                 // BM*KC
    float* sB    = sm + BM*KC;         // KC*257
    float* sBias = sB + KC*257;        // 256

    int tid = threadIdx.x;
    int rt = tid >> 5, ct = tid & 31;
    long r0 = (long)blockIdx.x * BM;

    sBias[tid] = bias ? bias[tid] : 0.f;

    float acc[8][8];
#pragma unroll
    for (int i = 0; i < 8; i++)
#pragma unroll
        for (int j = 0; j < 8; j++) acc[i][j] = 0.f;

    for (int k0 = 0; k0 < K; k0 += KC) {
#pragma unroll 4
        for (int t = tid; t < BM*KC; t += 256) {
            int row = t >> 6, kk = t & 63;
            int k = k0 + kk;
            long r = r0 + row;
            sA[t] = (k < K && r < rows) ? A[r*(long)lda + k] : 0.f;
        }
#pragma unroll 8
        for (int t = tid; t < 256*KC; t += 256) {
            int n = t >> 6, kk = t & 63;
            int k = k0 + kk;
            sB[kk*257 + n] = (k < K) ? B[(long)n*ldb + k] : 0.f;
        }
        __syncthreads();
#pragma unroll 8
        for (int kk = 0; kk < KC; kk++) {
            float a[8], bv[8];
#pragma unroll
            for (int i = 0; i < 8; i++) a[i] = sA[(rt*8 + i)*KC + kk];
#pragma unroll
            for (int j = 0; j < 8; j++) bv[j] = sB[kk*257 + ct + j*32];
#pragma unroll
            for (int i = 0; i < 8; i++)
#pragma unroll
                for (int j = 0; j < 8; j++) acc[i][j] = fmaf(a[i], bv[j], acc[i][j]);
        }
        __syncthreads();
    }
#pragma unroll
    for (int i = 0; i < 8; i++) {
        long row = r0 + rt*8 + i;
        if (row < rows) {
#pragma unroll
            for (int j = 0; j < 8; j++) {
                int col = ct + j*32;
                float v = acc[i][j] + sBias[col];
                if (act == 1) v = fmaxf(v, 0.f);
                C[row*256 + col] = v;
            }
        }
    }
}

// ---------------- f32x2 GEMM, K=256, N=256, Bt pre-transposed (k-major) ----------------
__global__ void __launch_bounds__(256,2) gemm_ffma2(
    const float* __restrict__ A,      // [rows][256]
    const float* __restrict__ Bt,     // [256][256] k-major
    const float* __restrict__ bias,
    float* __restrict__ C, int act)
{
    extern __shared__ float sm[];
    float* sA    = sm;                // 64*256 = 16384
    float* sPan  = sA + 64*256;       // 3*KCP*256 = 12288
    float* sBias = sPan + 3*KCP*256;  // 256

    int tid = threadIdx.x;
    int warp = tid >> 5, ct = tid & 31;
    int rbase = warp * 8;
    long r0 = (long)blockIdx.x * 64;

    sBias[tid] = bias ? bias[tid] : 0.f;
    // load A tile (coalesced float4)
    {
        const float4* g4 = (const float4*)(A + r0*256);
        float4* s4 = (float4*)sA;
#pragma unroll 4
        for (int i = tid; i < 64*64; i += 256) s4[i] = g4[i];
    }
    issue_panel(Bt + 0*KCP*256, sPan + 0*KCP*256, tid);
    issue_panel(Bt + 1*KCP*256, sPan + 1*KCP*256, tid);

    ull acc[8][4];
#pragma unroll
    for (int i = 0; i < 8; i++)
#pragma unroll
        for (int j = 0; j < 4; j++) acc[i][j] = 0ull;

    for (int p = 0; p < 16; p++) {
        if (p < 15) cp_wait<1>(); else cp_wait<0>();
        __syncthreads();
        if (p + 2 < 16)
            issue_panel(Bt + (p+2)*KCP*256, sPan + ((p+2)%3)*KCP*256, tid);
        compute_panel16<8>(sPan + (p%3)*KCP*256, sA, p*KCP, acc, rbase, ct);
    }

#pragma unroll
    for (int i = 0; i < 8; i++) {
        long row = r0 + rbase + i;
#pragma unroll
        for (int j = 0; j < 4; j++) {
            int col = 2*(ct + 32*j);
            float2 v = unpack2(acc[i][j]);
            v.x += sBias[col];
            v.y += sBias[col+1];
            if (act) { v.x = fmaxf(v.x, 0.f); v.y = fmaxf(v.y, 0.f); }
            *(float2*)(C + row*256 + col) = v;
        }
    }
}

// ---------------- 256x256 transpose: out[k][256+n] = in[n][ldin+k] ----------------
__global__ void transpose256(const float* __restrict__ in, int ldin, float* __restrict__ out)
{
    __shared__ float tl[32][33];
    int bx = blockIdx.x*32, by = blockIdx.y*32;  // bx: k, by: n
    int tx = threadIdx.x, ty = threadIdx.y;      // block(32,8)
#pragma unroll
    for (int r = 0; r < 4; r++)
        tl[ty + 8*r][tx] = in[(long)(by + ty + 8*r)*ldin + bx + tx];
    __syncthreads();
#pragma unroll
    for (int r = 0; r < 4; r++)
        out[(long)(bx + ty + 8*r)*256 + by + tx] = tl[tx][ty + 8*r];
}

// ---------------- gateE = mi @ embed^T  (SB x 20) ----------------
__global__ void __launch_bounds__(256) gatee_kernel(
    const float* __restrict__ mi, const float* __restrict__ embed, float* __restrict__ out)
{
    extern __shared__ float sm[];
    float* sMi = sm;            // 64*256
    float* sE  = sm + 64*256;   // 20*256
    int tid = threadIdx.x, ct = tid & 31;
    long r0 = (long)blockIdx.x * 64;
    {
        const float4* g4 = (const float4*)(mi + r0*256);
        float4* s4 = (float4*)sMi;
#pragma unroll 4
        for (int i = tid; i < 64*64; i += 256) s4[i] = g4[i];
        const float4* e4 = (const float4*)embed;
        float4* se4 = (float4*)sE;
        for (int i = tid; i < 20*64; i += 256) se4[i] = e4[i];
    }
    __syncthreads();
#pragma unroll
    for (int q = 0; q < 5; q++) {
        int o = q*256 + tid;            // 0..1279
        int row = o / 20, m = o % 20;
        float acc = 0.f;
#pragma unroll 8
        for (int k = 0; k < 256; k++) {
            int kr = (k + ct*8) & 255;  // rotate to avoid bank conflicts
            acc += sMi[row*256 + kr] * sE[m*256 + kr];
        }
        out[r0*20 + o] = acc;
    }
}

// ---------------- fused persistent scan (state SMEM-resident, weights cp.async) ----------------
__global__ void __launch_bounds__(256,1) scan_kernel(
    const float* __restrict__ Ut, const float* __restrict__ J1t,
    const float* __restrict__ U_b, const float* __restrict__ J_b,
    const float* __restrict__ prelu_a,
    const float* __restrict__ mi, const float* __restrict__ sentJ,
    const float* __restrict__ gateE, const float* __restrict__ keyJ,
    float* __restrict__ mem)
{
    extern __shared__ float sm[];
    float* sMem  = sm;                       // 80*256 = 20480
    float* sA1   = sMem + TROWS*256;         // 20480
    float* sPan  = sA1  + TROWS*256;         // 3*16*256 = 12288
    float* sSent = sPan + 3*KCP*256;         // 4*256
    float* sSJ   = sSent + 4*256;            // 4*256
    float* sUb   = sSJ   + 4*256;            // 256
    float* sJb   = sUb   + 256;              // 256

    int tid = threadIdx.x;
    int warp = tid >> 5, ct = tid & 31;
    int rbase = warp * RPT;
    float alpha = prelu_a[0];
    sUb[tid] = U_b[tid];
    sJb[tid] = J_b[tid];

    int t0 = (blockIdx.x     * NTILES) / SCAN_GRID;
    int t1 = ((blockIdx.x+1) * NTILES) / SCAN_GRID;

    for (int t = t0; t < t1; t++) {
        int r0 = t * TROWS;
        int b0 = t * 4;                       // 4 batches per tile exactly
        __syncthreads();                      // prev tile fully done
        {
            const float4* g4 = (const float4*)(mem + (size_t)r0*256);
            float4* s4 = (float4*)sMem;
#pragma unroll 4
            for (int i = tid; i < TROWS*64; i += 256) s4[i] = g4[i];
        }

        for (int s = 0; s < SEQ; s++) {
            __syncthreads();                  // prev epilogue done (sSJ), sMem tile loaded
            {
                const float4* g1 = (const float4*)(mi    + ((size_t)s*BSZ + b0)*256);
                const float4* g2 = (const float4*)(sentJ + ((size_t)s*BSZ + b0)*256);
                ((float4*)sSent)[tid] = g1[tid];   // 256 float4 = 4 batches
                ((float4*)sSJ)[tid]   = g2[tid];
            }
            // warm the panel pipeline (buffers 0,1 free by loop-barrier argument)
            issue_panel(Ut + 0*KCP*256, sPan + 0*KCP*256, tid);
            issue_panel(Ut + 1*KCP*256, sPan + 1*KCP*256, tid);
            __syncthreads();                  // sSent/sSJ visible

            // ---- gate (sent.mem in SMEM + precomputed sent.embed) ----
            float gv[RPT];
#pragma unroll
            for (int i = 0; i < RPT; i++) {
                int lr = rbase + i;
                const float* se = sSent + (lr/20)*256;
                float p = 0.f;
#pragma unroll
                for (int q = 0; q < 8; q++) {
                    int k = ct + q*32;
                    p += se[k] * sMem[lr*256 + k];
                }
#pragma unroll
                for (int o = 16; o > 0; o >>= 1) p += __shfl_xor_sync(0xffffffffu, p, o);
                p += gateE[(size_t)s*ROWS + r0 + lr];
                gv[i] = 1.f / (1.f + expf(-p));
            }

            ull acc[RPT][4];
#pragma unroll
            for (int i = 0; i < RPT; i++)
#pragma unroll
                for (int j = 0; j < 4; j++) acc[i][j] = 0ull;

            // ---- 32 panels: 16 of U (GEMM1 on sMem), 16 of J1 (GEMM2 on sA1) ----
            for (int p = 0; p < NPAN; p++) {
                if (p < NPAN-1) cp_wait<1>(); else cp_wait<0>();
                __syncthreads();
                int pn = p + 2;
                if (pn < NPAN) {
                    const float* src = (pn < 16) ? (Ut + pn*KCP*256)
                                                 : (J1t + (pn-16)*KCP*256);
                    issue_panel(src, sPan + (pn%3)*KCP*256, tid);
                }
                const float* A = (p < 16) ? sMem : sA1;
                compute_panel16<RPT>(sPan + (p%3)*KCP*256, A, (p & 15)*KCP, acc, rbase, ct);

                if (p == 15) {
                    // A1 = relu(acc + U_b), then reset acc for GEMM2
#pragma unroll
                    for (int i = 0; i < RPT; i++) {
#pragma unroll
                        for (int j = 0; j < 4; j++) {
                            int col = 2*(ct + 32*j);
                            float2 v = unpack2(acc[i][j]);
                            v.x = fmaxf(v.x + sUb[col],   0.f);
                            v.y = fmaxf(v.y + sUb[col+1], 0.f);
                            *(float2*)(sA1 + (rbase+i)*256 + col) = v;
                            acc[i][j] = 0ull;
                        }
                    }
                }
            }

            // ---- epilogue: prelu, gated update, normalize; sMem in place (warp-local) ----
#pragma unroll
            for (int i = 0; i < RPT; i++) {
                int lr = rbase + i;
                int m  = lr % MSLOT;
                float g = gv[i];
                const float* sj = sSJ + (lr/20)*256;
                const float* kj = keyJ + m*256;
                float u[8];
                float ss = 0.f;
#pragma unroll
                for (int j = 0; j < 4; j++) {
                    int col = 2*(ct + 32*j);
                    float2 c = unpack2(acc[i][j]);
                    float2 kv = *(const float2*)(kj + col);
                    float c0 = c.x + sJb[col]   + sj[col]   + kv.x;
                    float c1 = c.y + sJb[col+1] + sj[col+1] + kv.y;
                    c0 = c0 > 0.f ? c0 : alpha * c0;
                    c1 = c1 > 0.f ? c1 : alpha * c1;
                    float u0 = sMem[lr*256 + col]     + g * c0;
                    float u1 = sMem[lr*256 + col + 1] + g * c1;
                    u[2*j] = u0; u[2*j+1] = u1;
                    ss += u0*u0 + u1*u1;
                }
#pragma unroll
                for (int o = 16; o > 0; o >>= 1) ss += __shfl_xor_sync(0xffffffffu, ss, o);
                float inv = 1.f / (sqrtf(ss) + 1e-12f);
#pragma unroll
                for (int j = 0; j < 4; j++) {
                    int col = 2*(ct + 32*j);
                    float2 w; w.x = u[2*j]*inv; w.y = u[2*j+1]*inv;
                    *(float2*)(sMem + lr*256 + col) = w;
                }
            }
        }

        __syncthreads();
        {
            const float4* s4 = (const float4*)sMem;
            float4* g4 = (float4*)(mem + (size_t)r0*256);
#pragma unroll 4
            for (int i = tid; i < TROWS*64; i += 256) g4[i] = s4[i];
        }
    }
}

// ---------------- memories init: mem[b*20+m][d] = embed[m][d] ----------------
__global__ void init_mem_kernel(const float* __restrict__ embed, float* __restrict__ mem)
{
    long idx = (long)blockIdx.x * 256 + threadIdx.x;
    int d = idx & 255;
    long rm = idx >> 8;
    int m = (int)(rm % MSLOT);
    mem[idx] = embed[m*256 + d];
}

// ---------------- attention + concat ----------------
__global__ void __launch_bounds__(256) attn_kernel(
    const float* __restrict__ mem, const float* __restrict__ q, float* __restrict__ cat)
{
    __shared__ float sQ[256];
    __shared__ float sM[MSLOT*256];
    __shared__ float sE[MSLOT];
    int b = blockIdx.x, tid = threadIdx.x;
    sQ[tid] = q[(long)b*256 + tid];
    for (int t = tid; t < MSLOT*256; t += 256) sM[t] = mem[(long)b*MSLOT*256 + t];
    __syncthreads();
    int w = tid >> 5, l = tid & 31;
    for (int m = w; m < MSLOT; m += 8) {
        float p = 0.f;
        for (int k = l; k < 256; k += 32) p += sM[m*256 + k] * sQ[k];
#pragma unroll
        for (int o = 16; o > 0; o >>= 1) p += __shfl_xor_sync(0xffffffffu, p, o);
        if (l == 0) sE[m] = p;
    }
    __syncthreads();
    float mx = -1e30f;
    for (int m = 0; m < MSLOT; m++) mx = fmaxf(mx, sE[m]);
    float sum = 0.f;
    for (int m = 0; m < MSLOT; m++) sum += expf(sE[m] - mx);
    float att = 0.f;
    for (int m = 0; m < MSLOT; m++) att += sM[m*256 + tid] * expf(sE[m] - mx);
    att /= sum;
    cat[(long)b*512 + tid]       = sQ[tid];
    cat[(long)b*512 + 256 + tid] = att;
}

// ---------------- host launcher ----------------
extern "C" void kernel_launch(void* const* d_in, const int* in_sizes, int n_in,
                              void* d_out, int out_size)
{
    const float* memory_inputs = (const float*)d_in[0];
    const float* question      = (const float*)d_in[1];
    const float* C_w = (const float*)d_in[2];
    const float* C_b = (const float*)d_in[3];
    const float* Q_w = (const float*)d_in[4];
    const float* Q_b = (const float*)d_in[5];
    const float* H_w = (const float*)d_in[6];
    const float* H_b = (const float*)d_in[7];
    const float* U_w = (const float*)d_in[8];
    const float* U_b = (const float*)d_in[9];
    const float* V_w = (const float*)d_in[10];
    const float* V_b = (const float*)d_in[11];
    const float* W_w = (const float*)d_in[12];
    const float* W_b = (const float*)d_in[13];
    const float* J_w = (const float*)d_in[14];
    const float* J_b = (const float*)d_in[15];
    const float* prelu_a = (const float*)d_in[16];
    const float* embed   = (const float*)d_in[17];
    float* out = (float*)d_out;

    size_t gemm_smem  = (size_t)(BM*KC + KC*257 + 256) * sizeof(float);
    size_t gx2_smem   = (size_t)(64*256 + 3*KCP*256 + 256) * sizeof(float);
    size_t scan_smem  = (size_t)(TROWS*256*2 + 3*KCP*256 + 4*256*2 + 512) * sizeof(float);
    size_t gatee_smem = (size_t)(64*256 + 20*256) * sizeof(float);
    cudaFuncSetAttribute(gemm256,      cudaFuncAttributeMaxDynamicSharedMemorySize, (int)gemm_smem);
    cudaFuncSetAttribute(gemm_ffma2,   cudaFuncAttributeMaxDynamicSharedMemorySize, (int)gx2_smem);
    cudaFuncSetAttribute(scan_kernel,  cudaFuncAttributeMaxDynamicSharedMemorySize, (int)scan_smem);
    cudaFuncSetAttribute(gatee_kernel, cudaFuncAttributeMaxDynamicSharedMemorySize, (int)gatee_smem);

    float *mi, *tmp, *sentJ, *memb, *q, *a3, *keyJ, *cat, *gateE, *wT;
    cudaGetSymbolAddress((void**)&mi,    g_mi);
    cudaGetSymbolAddress((void**)&tmp,   g_tmp);
    cudaGetSymbolAddress((void**)&sentJ, g_sentJ);
    cudaGetSymbolAddress((void**)&memb,  g_mem);
    cudaGetSymbolAddress((void**)&q,     g_q);
    cudaGetSymbolAddress((void**)&a3,    g_a3);
    cudaGetSymbolAddress((void**)&keyJ,  g_keyJ);
    cudaGetSymbolAddress((void**)&cat,   g_cat);
    cudaGetSymbolAddress((void**)&gateE, g_gateE);
    cudaGetSymbolAddress((void**)&wT,    g_wT);
    float* Ut  = wT;
    float* J1t = wT + (size_t)HID*HID;
    float* Vt  = wT + 2*(size_t)HID*HID;
    float* J2t = wT + 3*(size_t)HID*HID;

    // weight transposes (one-time, tiny)
    dim3 tb(32, 8), tg(8, 8);
    transpose256<<<tg, tb>>>(U_w, 256, Ut);
    transpose256<<<tg, tb>>>(J_w, 768, J1t);
    transpose256<<<tg, tb>>>(V_w, 256, Vt);
    transpose256<<<tg, tb>>>(J_w + 256, 768, J2t);

    // init recurrent state
    init_mem_kernel<<<ROWS, 256>>>(embed, memb);

    // precompute
    gemm256<<<SB/BM, 256, gemm_smem>>>(memory_inputs, DIN, SB, DIN, C_w, DIN, C_b, mi, 1);
    gemm256<<<BSZ/BM, 256, gemm_smem>>>(question, QDIM, BSZ, QDIM, Q_w, QDIM, Q_b, q, 1);
    gatee_kernel<<<SB/64, 256, gatee_smem>>>(mi, embed, gateE);
    gemm_ffma2<<<SB/64, 256, gx2_smem>>>(mi, Vt, V_b, tmp, 1);
    gemm_ffma2<<<SB/64, 256, gx2_smem>>>(tmp, J2t, (const float*)0, sentJ, 0);
    gemm256<<<1, 256, gemm_smem>>>(embed, HID, MSLOT, HID, W_w, HID, W_b, a3, 1);
    gemm256<<<1, 256, gemm_smem>>>(a3, HID, MSLOT, HID, J_w + 512, 768, (const float*)0, keyJ, 0);

    // fused persistent scan
    scan_kernel<<<SCAN_GRID, 256, scan_smem>>>(Ut, J1t, U_b, J_b, prelu_a,
                                               mi, sentJ, gateE, keyJ, memb);

    // attention + concat, then final projection
    attn_kernel<<<BSZ, 256>>>(memb, q, cat);
    gemm256<<<BSZ/BM, 256, gemm_smem>>>(cat, 2*HID, BSZ, 2*HID, H_w, 2*HID, H_b, out, 1);
}